// round 5
// baseline (speedup 1.0000x reference)
#include <cuda_runtime.h>
#include <cuda_bf16.h>
#include <cstdint>

#define B 2
#define L 1536
#define D 768
#define H 12
#define DK 64
#define BLD ((size_t)B * L * D)
#define DD  ((size_t)D * D)

// ---------------------------------------------------------------------------
// Scratch (allocation-free rule: static __device__ arrays)
// ---------------------------------------------------------------------------
__device__ __nv_bfloat16 g_xqh[BLD], g_xql[BLD];
__device__ __nv_bfloat16 g_xkh[BLD], g_xkl[BLD];
__device__ __nv_bfloat16 g_wqh[DD],  g_wql[DD];
__device__ __nv_bfloat16 g_wkh[DD],  g_wkl[DD];
__device__ __nv_bfloat16 g_qh[BLD], g_ql[BLD];
__device__ __nv_bfloat16 g_kh[BLD], g_kl[BLD];

__device__ __forceinline__ uint32_t smem_u32(const void* p) {
    uint32_t a;
    asm("{ .reg .u64 t; cvta.to.shared.u64 t, %1; cvt.u32.u64 %0, t; }" : "=r"(a) : "l"(p));
    return a;
}
__device__ __forceinline__ void ldsm_x4(uint32_t addr, uint32_t& r0, uint32_t& r1,
                                        uint32_t& r2, uint32_t& r3) {
    asm volatile("ldmatrix.sync.aligned.m8n8.x4.shared.b16 {%0,%1,%2,%3}, [%4];"
                 : "=r"(r0), "=r"(r1), "=r"(r2), "=r"(r3) : "r"(addr));
}
__device__ __forceinline__ void ldsm_x2(uint32_t addr, uint32_t& r0, uint32_t& r1) {
    asm volatile("ldmatrix.sync.aligned.m8n8.x2.shared.b16 {%0,%1}, [%2];"
                 : "=r"(r0), "=r"(r1) : "r"(addr));
}
__device__ __forceinline__ void mma_bf16(float* c, const uint32_t* a, const uint32_t* b) {
    asm volatile(
        "mma.sync.aligned.m16n8k16.row.col.f32.bf16.bf16.f32 "
        "{%0,%1,%2,%3}, {%4,%5,%6,%7}, {%8,%9}, {%0,%1,%2,%3};"
        : "+f"(c[0]), "+f"(c[1]), "+f"(c[2]), "+f"(c[3])
        : "r"(a[0]), "r"(a[1]), "r"(a[2]), "r"(a[3]), "r"(b[0]), "r"(b[1]));
}
__device__ __forceinline__ void cpa16(uint32_t s, const void* g) {
    asm volatile("cp.async.cg.shared.global [%0], [%1], 16;" :: "r"(s), "l"(g));
}
#define CPA_COMMIT() asm volatile("cp.async.commit_group;" ::: "memory")
#define CPA_WAIT1()  asm volatile("cp.async.wait_group 1;" ::: "memory")
#define CPA_WAIT0()  asm volatile("cp.async.wait_group 0;" ::: "memory")

// ---------------------------------------------------------------------------
// Phase 0: fp32 -> bf16 hi/lo split of one source array (4 launches)
// ---------------------------------------------------------------------------
__global__ void split_src_kernel(const float* __restrict__ src, int which, int n4)
{
    int i = blockIdx.x * blockDim.x + threadIdx.x;
    if (i >= n4) return;

    __nv_bfloat16* dh;
    __nv_bfloat16* dl;
    switch (which) {
        case 0: dh = g_xqh; dl = g_xql; break;
        case 1: dh = g_xkh; dl = g_xkl; break;
        case 2: dh = g_wqh; dl = g_wql; break;
        default: dh = g_wkh; dl = g_wkl; break;
    }

    float4 v = ((const float4*)src)[i];
    __nv_bfloat16 h[4], l[4];
    const float* f = &v.x;
    #pragma unroll
    for (int j = 0; j < 4; j++) {
        h[j] = __float2bfloat16(f[j]);
        l[j] = __float2bfloat16(f[j] - __bfloat162float(h[j]));
    }
    ((uint2*)dh)[i] = *(uint2*)h;
    ((uint2*)dl)[i] = *(uint2*)l;
}

// ---------------------------------------------------------------------------
// Phase 1: projection via HMMA bf16x3 (unchanged from R4).
// ---------------------------------------------------------------------------
#define RP 72
#define PROJ_SM_A (128 * RP)
#define PROJ_SM_B (256 * RP)
#define PROJ_SM_BYTES ((2 * PROJ_SM_A + 2 * PROJ_SM_B) * 2)

__global__ void __launch_bounds__(512, 1) proj_mma_kernel(
    const float* __restrict__ biasq, const float* __restrict__ biask)
{
    extern __shared__ __nv_bfloat16 sm[];
    __nv_bfloat16* sAh = sm;
    __nv_bfloat16* sAl = sm + PROJ_SM_A;
    __nv_bfloat16* sBh = sm + 2 * PROJ_SM_A;
    __nv_bfloat16* sBl = sm + 2 * PROJ_SM_A + PROJ_SM_B;

    int nt = blockIdx.x, mt = blockIdx.y, which = blockIdx.z;
    int tid = threadIdx.x;
    int wid = tid >> 5, lane = tid & 31;

    const __nv_bfloat16* xh = which ? g_xkh : g_xqh;
    const __nv_bfloat16* xl = which ? g_xkl : g_xql;
    const __nv_bfloat16* wh = which ? g_wkh : g_wqh;
    const __nv_bfloat16* wl = which ? g_wkl : g_wql;
    __nv_bfloat16* oh = which ? g_kh : g_qh;
    __nv_bfloat16* ol = which ? g_kl : g_ql;
    const float* bias = which ? biask : biasq;

    int wm = (wid & 1) * 64;
    int wn = (wid >> 1) * 32;

    float acc[4][4][4];
    #pragma unroll
    for (int i = 0; i < 4; i++)
        #pragma unroll
        for (int j = 0; j < 4; j++)
            #pragma unroll
            for (int r = 0; r < 4; r++) acc[i][j][r] = 0.f;

    uint32_t sAh_b = smem_u32(sAh), sAl_b = smem_u32(sAl);
    uint32_t sBh_b = smem_u32(sBh), sBl_b = smem_u32(sBl);

    int a_row = lane & 15;
    int a_kh8 = (lane >> 4) * 8;
    int b_row = lane & 7;
    int b_kh8 = ((lane >> 3) & 1) * 8;

    for (int kc = 0; kc < D; kc += 64) {
        __syncthreads();
        #pragma unroll
        for (int it = 0; it < 2; it++) {
            int idx = tid + it * 512;
            int row = idx >> 3;
            int c8  = (idx & 7) * 8;
            size_t g = (size_t)(mt * 128 + row) * D + kc + c8;
            *(uint4*)(sAh + row * RP + c8) = *(const uint4*)(xh + g);
            *(uint4*)(sAl + row * RP + c8) = *(const uint4*)(xl + g);
        }
        #pragma unroll
        for (int it = 0; it < 4; it++) {
            int idx = tid + it * 512;
            int row = idx >> 3;
            int c8  = (idx & 7) * 8;
            size_t g = (size_t)(nt * 256 + row) * D + kc + c8;
            *(uint4*)(sBh + row * RP + c8) = *(const uint4*)(wh + g);
            *(uint4*)(sBl + row * RP + c8) = *(const uint4*)(wl + g);
        }
        __syncthreads();

        #pragma unroll
        for (int ks = 0; ks < 4; ks++) {
            int kb = ks * 16;
            uint32_t ah[4][4], al[4][4];
            #pragma unroll
            for (int i = 0; i < 4; i++) {
                uint32_t off = (uint32_t)((wm + i * 16 + a_row) * RP + kb + a_kh8) * 2;
                ldsm_x4(sAh_b + off, ah[i][0], ah[i][1], ah[i][2], ah[i][3]);
                ldsm_x4(sAl_b + off, al[i][0], al[i][1], al[i][2], al[i][3]);
            }
            #pragma unroll
            for (int j = 0; j < 4; j++) {
                uint32_t off = (uint32_t)((wn + j * 8 + b_row) * RP + kb + b_kh8) * 2;
                uint32_t bh[2], bl[2];
                ldsm_x2(sBh_b + off, bh[0], bh[1]);
                ldsm_x2(sBl_b + off, bl[0], bl[1]);
                #pragma unroll
                for (int i = 0; i < 4; i++) {
                    mma_bf16(acc[i][j], ah[i], bh);
                    mma_bf16(acc[i][j], ah[i], bl);
                    mma_bf16(acc[i][j], al[i], bh);
                }
            }
        }
    }

    int r0 = lane >> 2;
    int cp = (lane & 3) * 2;
    #pragma unroll
    for (int i = 0; i < 4; i++) {
        int grow0 = mt * 128 + wm + i * 16 + r0;
        #pragma unroll
        for (int j = 0; j < 4; j++) {
            int gcol = nt * 256 + wn + j * 8 + cp;
            float2 bv = *(const float2*)(bias + gcol);
            #pragma unroll
            for (int half = 0; half < 2; half++) {
                float v0 = acc[i][j][half * 2 + 0] + bv.x;
                float v1 = acc[i][j][half * 2 + 1] + bv.y;
                __nv_bfloat16 h0 = __float2bfloat16(v0);
                __nv_bfloat16 h1 = __float2bfloat16(v1);
                __nv_bfloat16 l0 = __float2bfloat16(v0 - __bfloat162float(h0));
                __nv_bfloat16 l1 = __float2bfloat16(v1 - __bfloat162float(h1));
                size_t addr = (size_t)(grow0 + half * 8) * D + gcol;
                __nv_bfloat16 hp[2] = {h0, h1}, lp[2] = {l0, l1};
                *(uint32_t*)(oh + addr) = *(uint32_t*)hp;
                *(uint32_t*)(ol + addr) = *(uint32_t*)lp;
            }
        }
    }
}

// ---------------------------------------------------------------------------
// Phase 2 (FUSED): scores + entmax-1.5 + head-average, no gmem score scratch.
// CTA = (b, 16 q-rows), 512 thr = 16 warps. For each head: HMMA the 16x1536
// z-slab into smem (K tiles double-buffered via cp.async), then warp w runs
// Newton entmax on row w and accumulates sum_h p/H in registers.
// ---------------------------------------------------------------------------
#define QR 16                          // q rows per CTA
#define SLAB_PITCH 1540                // floats; row*4 mod 32 spreads banks
// smem layout (bf16 element offsets)
#define S_QH   0
#define S_QL   (QR * RP)               // 1152
#define S_K0H  (2 * QR * RP)           // 2304
#define S_K0L  (S_K0H + 128 * RP)
#define S_K1H  (S_K0H + 2 * 128 * RP)
#define S_K1L  (S_K0H + 3 * 128 * RP)
#define S_BF16_END (S_K0H + 4 * 128 * RP)          // 39168 elems
#define SLAB_F_OFF (S_BF16_END / 2)                 // float index = 19584
#define FUSED_SM_BYTES (S_BF16_END * 2 + QR * SLAB_PITCH * 4)   // 176,896

__global__ void __launch_bounds__(512, 1) fused_scores_entmax_kernel(
    const int* __restrict__ mask, float* __restrict__ out)
{
    extern __shared__ __nv_bfloat16 sm[];
    float* slab = (float*)sm + SLAB_F_OFF;

    const int qt = blockIdx.x;                 // 0..95
    const int b  = blockIdx.y;                 // 0..1
    const int tid = threadIdx.x;
    const int w = tid >> 5, lane = tid & 31;

    const uint32_t sm_b = smem_u32(sm);
    const uint32_t sQh_b = sm_b + S_QH * 2;
    const uint32_t sQl_b = sm_b + S_QL * 2;
    const uint32_t sKh_b[2] = { sm_b + S_K0H * 2, sm_b + S_K1H * 2 };
    const uint32_t sKl_b[2] = { sm_b + S_K0L * 2, sm_b + S_K1L * 2 };

    // mask bits: bit i <-> column lane + i*32
    unsigned long long vbits = 0ull;
    #pragma unroll
    for (int i = 0; i < 48; i++)
        if (mask[b * L + lane + i * 32] != 0) vbits |= 1ull << i;

    float acc[48];
    #pragma unroll
    for (int e = 0; e < 48; e++) acc[e] = 0.f;

    const float scale = 1.0f / 16.0f;          // 1/(2*sqrt(dk))
    const float invH = 1.0f / 12.0f;

    // ldmatrix addressing
    const int a_row = lane & 15;
    const int a_kh8 = (lane >> 4) * 8;
    const int b_row = lane & 7;
    const int b_kh8 = ((lane >> 3) & 1) * 8;
    const uint32_t a_off = (uint32_t)(a_row * RP + a_kh8) * 2;
    const uint32_t b_off = (uint32_t)((w * 8 + b_row) * RP + b_kh8) * 2;

    for (int h = 0; h < H; h++) {
        const __nv_bfloat16* qhb = g_qh + (size_t)(b * L + qt * QR) * D + h * DK;
        const __nv_bfloat16* qlb = g_ql + (size_t)(b * L + qt * QR) * D + h * DK;
        const __nv_bfloat16* khb = g_kh + (size_t)b * L * D + h * DK;
        const __nv_bfloat16* klb = g_kl + (size_t)b * L * D + h * DK;

        // load Q tile (plain): 16 rows x 64, hi+lo -> 128 uint4 each
        if (tid < 128) {
            int row = tid >> 3;
            int c8  = (tid & 7) * 8;
            *(uint4*)(sm + S_QH + row * RP + c8) = *(const uint4*)(qhb + (size_t)row * D + c8);
            *(uint4*)(sm + S_QL + row * RP + c8) = *(const uint4*)(qlb + (size_t)row * D + c8);
        }

        // prefetch K tile 0 into buffer 0
        {
            #pragma unroll
            for (int it = 0; it < 2; it++) {
                int idx = tid + it * 512;
                int row = idx >> 3;
                int c8  = (idx & 7) * 8;
                const size_t g = (size_t)row * D + c8;
                cpa16(sKh_b[0] + (uint32_t)(row * RP + c8) * 2, khb + g);
                cpa16(sKl_b[0] + (uint32_t)(row * RP + c8) * 2, klb + g);
            }
            CPA_COMMIT();
        }

        int buf = 0;
        for (int kt = 0; kt < 12; kt++) {
            if (kt < 11) {
                #pragma unroll
                for (int it = 0; it < 2; it++) {
                    int idx = tid + it * 512;
                    int row = idx >> 3;
                    int c8  = (idx & 7) * 8;
                    const size_t g = (size_t)((kt + 1) * 128 + row) * D + c8;
                    cpa16(sKh_b[buf ^ 1] + (uint32_t)(row * RP + c8) * 2, khb + g);
                    cpa16(sKl_b[buf ^ 1] + (uint32_t)(row * RP + c8) * 2, klb + g);
                }
                CPA_COMMIT();
                CPA_WAIT1();
            } else {
                CPA_WAIT0();
            }
            __syncthreads();   // K(kt) visible; prev entmax/slab users done

            // MMA: warp w computes 16 rows x 8 cols (cols kt*128 + w*8)
            float c[4] = {0.f, 0.f, 0.f, 0.f};
            #pragma unroll
            for (int ks = 0; ks < 4; ks++) {
                uint32_t ka = (uint32_t)(ks * 16) * 2;
                uint32_t ah[4], al[4], bh2[2], bl2[2];
                ldsm_x4(sQh_b + a_off + ka, ah[0], ah[1], ah[2], ah[3]);
                ldsm_x4(sQl_b + a_off + ka, al[0], al[1], al[2], al[3]);
                ldsm_x2(sKh_b[buf] + b_off + ka, bh2[0], bh2[1]);
                ldsm_x2(sKl_b[buf] + b_off + ka, bl2[0], bl2[1]);
                mma_bf16(c, ah, bh2);
                mma_bf16(c, ah, bl2);
                mma_bf16(c, al, bh2);
            }
            // epilogue -> slab
            {
                int r0 = lane >> 2;
                int cp = (lane & 3) * 2;
                int colb = kt * 128 + w * 8 + cp;
                *(float2*)(slab + r0 * SLAB_PITCH + colb) =
                    make_float2(c[0] * scale, c[1] * scale);
                *(float2*)(slab + (r0 + 8) * SLAB_PITCH + colb) =
                    make_float2(c[2] * scale, c[3] * scale);
            }
            __syncthreads();   // slab patch done; buf reusable next-next iter
            buf ^= 1;
        }

        // ---- entmax on row w (one warp per row), accumulate ----
        {
            const float* zrow = slab + w * SLAB_PITCH;
            float z[48];
            float m = -1e30f;
            #pragma unroll
            for (int i = 0; i < 48; i++) {
                float v = zrow[lane + i * 32];
                z[i] = ((vbits >> i) & 1ull) ? v : -1e30f;
                m = fmaxf(m, z[i]);
            }
            #pragma unroll
            for (int o = 16; o; o >>= 1) m = fmaxf(m, __shfl_xor_sync(0xffffffffu, m, o));

            float tau = m - 1.0f;
            for (int it = 0; it < 24; it++) {
                float s0 = 0.f, s1 = 0.f;
                #pragma unroll
                for (int e = 0; e < 48; e++) {
                    float d = z[e] - tau;
                    if (d > 0.f) { s0 = fmaf(d, d, s0); s1 += d; }
                }
                #pragma unroll
                for (int o = 16; o; o >>= 1) {
                    s0 += __shfl_xor_sync(0xffffffffu, s0, o);
                    s1 += __shfl_xor_sync(0xffffffffu, s1, o);
                }
                if (s1 <= 0.f) break;
                float step = (s0 - 1.0f) / (2.0f * s1);
                tau += step;
                if (fabsf(step) <= 5e-7f) break;
            }

            #pragma unroll
            for (int e = 0; e < 48; e++) {
                float d = z[e] - tau;
                if (d > 0.f) acc[e] = fmaf(d * d, invH, acc[e]);
            }
        }
        // next head: Q load + K prefetch touch regions disjoint from slab;
        // the first __syncthreads in the kt loop orders slab reuse.
    }

    // write output: row qt*16 + w
    float* orow = out + ((size_t)b * L + qt * QR + w) * L;
    #pragma unroll
    for (int i = 0; i < 48; i++)
        orow[lane + i * 32] = acc[i];
}

// ---------------------------------------------------------------------------
extern "C" void kernel_launch(void* const* d_in, const int* in_sizes, int n_in,
                              void* d_out, int out_size)
{
    const float* query = (const float*)d_in[0];
    const float* key   = (const float*)d_in[1];
    const int*   mask  = (const int*)d_in[2];
    const float* wq_w  = (const float*)d_in[3];
    const float* wq_b  = (const float*)d_in[4];
    const float* wk_w  = (const float*)d_in[5];
    const float* wk_b  = (const float*)d_in[6];
    float* out = (float*)d_out;

    (void)in_sizes; (void)n_in; (void)out_size;

    cudaFuncSetAttribute(proj_mma_kernel,
                         cudaFuncAttributeMaxDynamicSharedMemorySize, PROJ_SM_BYTES);
    cudaFuncSetAttribute(fused_scores_entmax_kernel,
                         cudaFuncAttributeMaxDynamicSharedMemorySize, FUSED_SM_BYTES);

    {
        int n4_x = (int)(BLD / 4);
        int n4_w = (int)(DD / 4);
        split_src_kernel<<<(n4_x + 255) / 256, 256>>>(query, 0, n4_x);
        split_src_kernel<<<(n4_x + 255) / 256, 256>>>(key,   1, n4_x);
        split_src_kernel<<<(n4_w + 255) / 256, 256>>>(wq_w,  2, n4_w);
        split_src_kernel<<<(n4_w + 255) / 256, 256>>>(wk_w,  3, n4_w);
    }

    dim3 pgrid(D / 256, (B * L) / 128, 2);       // (3, 24, 2)
    proj_mma_kernel<<<pgrid, 512, PROJ_SM_BYTES>>>(wq_b, wk_b);

    dim3 fgrid(L / QR, B);                       // (96, 2)
    fused_scores_entmax_kernel<<<fgrid, 512, FUSED_SM_BYTES>>>(mask, out);
}

// round 6
// speedup vs baseline: 1.5564x; 1.5564x over previous
#include <cuda_runtime.h>
#include <cuda_bf16.h>
#include <cstdint>

#define B 2
#define L 1536
#define D 768
#define H 12
#define DK 64
#define BLD ((size_t)B * L * D)
#define DD  ((size_t)D * D)

// ---------------------------------------------------------------------------
// Scratch (allocation-free rule: static __device__ arrays)
// ---------------------------------------------------------------------------
__device__ __nv_bfloat16 g_xqh[BLD], g_xql[BLD];
__device__ __nv_bfloat16 g_xkh[BLD], g_xkl[BLD];
__device__ __nv_bfloat16 g_wqh[DD],  g_wql[DD];
__device__ __nv_bfloat16 g_wkh[DD],  g_wkl[DD];
__device__ __nv_bfloat16 g_qh[BLD], g_ql[BLD];
__device__ __nv_bfloat16 g_kh[BLD], g_kl[BLD];
__device__ float g_s[(size_t)B * H * L * L];                // 226.5 MB

__device__ __forceinline__ uint32_t smem_u32(const void* p) {
    uint32_t a;
    asm("{ .reg .u64 t; cvta.to.shared.u64 t, %1; cvt.u32.u64 %0, t; }" : "=r"(a) : "l"(p));
    return a;
}
__device__ __forceinline__ void ldsm_x4(uint32_t addr, uint32_t& r0, uint32_t& r1,
                                        uint32_t& r2, uint32_t& r3) {
    asm volatile("ldmatrix.sync.aligned.m8n8.x4.shared.b16 {%0,%1,%2,%3}, [%4];"
                 : "=r"(r0), "=r"(r1), "=r"(r2), "=r"(r3) : "r"(addr));
}
__device__ __forceinline__ void ldsm_x2(uint32_t addr, uint32_t& r0, uint32_t& r1) {
    asm volatile("ldmatrix.sync.aligned.m8n8.x2.shared.b16 {%0,%1}, [%2];"
                 : "=r"(r0), "=r"(r1) : "r"(addr));
}
__device__ __forceinline__ void mma_bf16(float* c, const uint32_t* a, const uint32_t* b) {
    asm volatile(
        "mma.sync.aligned.m16n8k16.row.col.f32.bf16.bf16.f32 "
        "{%0,%1,%2,%3}, {%4,%5,%6,%7}, {%8,%9}, {%0,%1,%2,%3};"
        : "+f"(c[0]), "+f"(c[1]), "+f"(c[2]), "+f"(c[3])
        : "r"(a[0]), "r"(a[1]), "r"(a[2]), "r"(a[3]), "r"(b[0]), "r"(b[1]));
}
__device__ __forceinline__ void cpa16(uint32_t s, const void* g) {
    asm volatile("cp.async.cg.shared.global [%0], [%1], 16;" :: "r"(s), "l"(g));
}
#define CPA_COMMIT() asm volatile("cp.async.commit_group;" ::: "memory")
#define CPA_WAIT1()  asm volatile("cp.async.wait_group 1;" ::: "memory")
#define CPA_WAIT0()  asm volatile("cp.async.wait_group 0;" ::: "memory")

// ---------------------------------------------------------------------------
// Phase 0: fp32 -> bf16 hi/lo split of one source array (4 launches)
// ---------------------------------------------------------------------------
__global__ void split_src_kernel(const float* __restrict__ src, int which, int n4)
{
    int i = blockIdx.x * blockDim.x + threadIdx.x;
    if (i >= n4) return;

    __nv_bfloat16* dh;
    __nv_bfloat16* dl;
    switch (which) {
        case 0: dh = g_xqh; dl = g_xql; break;
        case 1: dh = g_xkh; dl = g_xkl; break;
        case 2: dh = g_wqh; dl = g_wql; break;
        default: dh = g_wkh; dl = g_wkl; break;
    }

    float4 v = ((const float4*)src)[i];
    __nv_bfloat16 h[4], l[4];
    const float* f = &v.x;
    #pragma unroll
    for (int j = 0; j < 4; j++) {
        h[j] = __float2bfloat16(f[j]);
        l[j] = __float2bfloat16(f[j] - __bfloat162float(h[j]));
    }
    ((uint2*)dh)[i] = *(uint2*)h;
    ((uint2*)dl)[i] = *(uint2*)l;
}

// ---------------------------------------------------------------------------
// Phase 1: projection via HMMA bf16x3, cp.async double-buffered K loop.
// C[3072, 768] = X @ W^T + bias, output split to bf16 hi/lo.
// CTA tile 128(M) x 256(N), 512 thr, K chunks of 64, 2 smem buffers.
// ---------------------------------------------------------------------------
#define RP 72
#define P_AH 0
#define P_AL (128 * RP)
#define P_BH (2 * 128 * RP)
#define P_BL (2 * 128 * RP + 256 * RP)
#define PROJ_BUF (2 * 128 * RP + 2 * 256 * RP)      // 55296 bf16 elems / buffer
#define PROJ_SM_BYTES (2 * PROJ_BUF * 2)             // 221,184 B

__global__ void __launch_bounds__(512, 1) proj_mma_kernel(
    const float* __restrict__ biasq, const float* __restrict__ biask)
{
    extern __shared__ __nv_bfloat16 sm[];
    const uint32_t sm_b = smem_u32(sm);

    int nt = blockIdx.x, mt = blockIdx.y, which = blockIdx.z;
    int tid = threadIdx.x;
    int wid = tid >> 5, lane = tid & 31;

    const __nv_bfloat16* xh = which ? g_xkh : g_xqh;
    const __nv_bfloat16* xl = which ? g_xkl : g_xql;
    const __nv_bfloat16* wh = which ? g_wkh : g_wqh;
    const __nv_bfloat16* wl = which ? g_wkl : g_wql;
    __nv_bfloat16* oh = which ? g_kh : g_qh;
    __nv_bfloat16* ol = which ? g_kl : g_ql;
    const float* bias = which ? biask : biasq;

    int wm = (wid & 1) * 64;
    int wn = (wid >> 1) * 32;

    float acc[4][4][4];
    #pragma unroll
    for (int i = 0; i < 4; i++)
        #pragma unroll
        for (int j = 0; j < 4; j++)
            #pragma unroll
            for (int r = 0; r < 4; r++) acc[i][j][r] = 0.f;

    int a_row = lane & 15;
    int a_kh8 = (lane >> 4) * 8;
    int b_row = lane & 7;
    int b_kh8 = ((lane >> 3) & 1) * 8;

    // per-thread load coordinates (reused every chunk)
    int lrowA[2], lc8A[2], lrowB[4], lc8B[4];
    #pragma unroll
    for (int it = 0; it < 2; it++) { int idx = tid + it * 512; lrowA[it] = idx >> 3; lc8A[it] = (idx & 7) * 8; }
    #pragma unroll
    for (int it = 0; it < 4; it++) { int idx = tid + it * 512; lrowB[it] = idx >> 3; lc8B[it] = (idx & 7) * 8; }

    auto prefetch = [&](int kc, int pb) {
        uint32_t base = sm_b + (uint32_t)pb * PROJ_BUF * 2;
        #pragma unroll
        for (int it = 0; it < 2; it++) {
            size_t g = (size_t)(mt * 128 + lrowA[it]) * D + kc + lc8A[it];
            uint32_t so = (uint32_t)(lrowA[it] * RP + lc8A[it]) * 2;
            cpa16(base + P_AH * 2 + so, xh + g);
            cpa16(base + P_AL * 2 + so, xl + g);
        }
        #pragma unroll
        for (int it = 0; it < 4; it++) {
            size_t g = (size_t)(nt * 256 + lrowB[it]) * D + kc + lc8B[it];
            uint32_t so = (uint32_t)(lrowB[it] * RP + lc8B[it]) * 2;
            cpa16(base + P_BH * 2 + so, wh + g);
            cpa16(base + P_BL * 2 + so, wl + g);
        }
        CPA_COMMIT();
    };

    prefetch(0, 0);

    int buf = 0;
    for (int kci = 0; kci < 12; kci++) {
        if (kci < 11) { prefetch((kci + 1) * 64, buf ^ 1); CPA_WAIT1(); }
        else          { CPA_WAIT0(); }
        __syncthreads();

        uint32_t base = sm_b + (uint32_t)buf * PROJ_BUF * 2;
        uint32_t sAh_b = base + P_AH * 2, sAl_b = base + P_AL * 2;
        uint32_t sBh_b = base + P_BH * 2, sBl_b = base + P_BL * 2;

        #pragma unroll
        for (int ks = 0; ks < 4; ks++) {
            int kb = ks * 16;
            uint32_t ah[4][4], al[4][4];
            #pragma unroll
            for (int i = 0; i < 4; i++) {
                uint32_t off = (uint32_t)((wm + i * 16 + a_row) * RP + kb + a_kh8) * 2;
                ldsm_x4(sAh_b + off, ah[i][0], ah[i][1], ah[i][2], ah[i][3]);
                ldsm_x4(sAl_b + off, al[i][0], al[i][1], al[i][2], al[i][3]);
            }
            #pragma unroll
            for (int j = 0; j < 4; j++) {
                uint32_t off = (uint32_t)((wn + j * 8 + b_row) * RP + kb + b_kh8) * 2;
                uint32_t bh[2], bl[2];
                ldsm_x2(sBh_b + off, bh[0], bh[1]);
                ldsm_x2(sBl_b + off, bl[0], bl[1]);
                #pragma unroll
                for (int i = 0; i < 4; i++) {
                    mma_bf16(acc[i][j], ah[i], bh);
                    mma_bf16(acc[i][j], ah[i], bl);
                    mma_bf16(acc[i][j], al[i], bh);
                }
            }
        }
        __syncthreads();   // compute done before buf gets overwritten
        buf ^= 1;
    }

    int r0 = lane >> 2;
    int cp = (lane & 3) * 2;
    #pragma unroll
    for (int i = 0; i < 4; i++) {
        int grow0 = mt * 128 + wm + i * 16 + r0;
        #pragma unroll
        for (int j = 0; j < 4; j++) {
            int gcol = nt * 256 + wn + j * 8 + cp;
            float2 bv = *(const float2*)(bias + gcol);
            #pragma unroll
            for (int half = 0; half < 2; half++) {
                float v0 = acc[i][j][half * 2 + 0] + bv.x;
                float v1 = acc[i][j][half * 2 + 1] + bv.y;
                __nv_bfloat16 h0 = __float2bfloat16(v0);
                __nv_bfloat16 h1 = __float2bfloat16(v1);
                __nv_bfloat16 l0 = __float2bfloat16(v0 - __bfloat162float(h0));
                __nv_bfloat16 l1 = __float2bfloat16(v1 - __bfloat162float(h1));
                size_t addr = (size_t)(grow0 + half * 8) * D + gcol;
                __nv_bfloat16 hp[2] = {h0, h1}, lp[2] = {l0, l1};
                *(uint32_t*)(oh + addr) = *(uint32_t*)hp;
                *(uint32_t*)(ol + addr) = *(uint32_t*)lp;
            }
        }
    }
}

// ---------------------------------------------------------------------------
// Phase 2: scores via HMMA bf16x3 (R4 version).
// CTA tile 128(q) x 256(k) x 64(dk), 512 thr. grid (6 kt, 12 qt, 24 bh)
// ---------------------------------------------------------------------------
#define SC_SM_Q (128 * RP)
#define SC_SM_K (256 * RP)
#define SC_SM_BYTES ((2 * SC_SM_Q + 2 * SC_SM_K) * 2)

__global__ void __launch_bounds__(512, 1) scores_mma_kernel()
{
    extern __shared__ __nv_bfloat16 sm[];
    __nv_bfloat16* sQh = sm;
    __nv_bfloat16* sQl = sm + SC_SM_Q;
    __nv_bfloat16* sKh = sm + 2 * SC_SM_Q;
    __nv_bfloat16* sKl = sm + 2 * SC_SM_Q + SC_SM_K;

    int kt = blockIdx.x, qt = blockIdx.y, bh = blockIdx.z;
    int b = bh / H, h = bh % H;
    int tid = threadIdx.x;
    int wid = tid >> 5, lane = tid & 31;

    {
        const __nv_bfloat16* qhb = g_qh + (size_t)(b * L + qt * 128) * D + h * DK;
        const __nv_bfloat16* qlb = g_ql + (size_t)(b * L + qt * 128) * D + h * DK;
        const __nv_bfloat16* khb = g_kh + (size_t)(b * L + kt * 256) * D + h * DK;
        const __nv_bfloat16* klb = g_kl + (size_t)(b * L + kt * 256) * D + h * DK;

        #pragma unroll
        for (int it = 0; it < 2; it++) {
            int idx = tid + it * 512;
            int row = idx >> 3;
            int c8  = (idx & 7) * 8;
            *(uint4*)(sQh + row * RP + c8) = *(const uint4*)(qhb + (size_t)row * D + c8);
            *(uint4*)(sQl + row * RP + c8) = *(const uint4*)(qlb + (size_t)row * D + c8);
        }
        #pragma unroll
        for (int it = 0; it < 4; it++) {
            int idx = tid + it * 512;
            int row = idx >> 3;
            int c8  = (idx & 7) * 8;
            *(uint4*)(sKh + row * RP + c8) = *(const uint4*)(khb + (size_t)row * D + c8);
            *(uint4*)(sKl + row * RP + c8) = *(const uint4*)(klb + (size_t)row * D + c8);
        }
    }
    __syncthreads();

    int wm = (wid & 1) * 64;
    int wn = (wid >> 1) * 32;

    float acc[4][4][4];
    #pragma unroll
    for (int i = 0; i < 4; i++)
        #pragma unroll
        for (int j = 0; j < 4; j++)
            #pragma unroll
            for (int r = 0; r < 4; r++) acc[i][j][r] = 0.f;

    uint32_t sQh_b = smem_u32(sQh), sQl_b = smem_u32(sQl);
    uint32_t sKh_b = smem_u32(sKh), sKl_b = smem_u32(sKl);

    int a_row = lane & 15;
    int a_kh8 = (lane >> 4) * 8;
    int b_row = lane & 7;
    int b_kh8 = ((lane >> 3) & 1) * 8;

    #pragma unroll
    for (int ks = 0; ks < 4; ks++) {
        int kb = ks * 16;
        uint32_t ah[4][4], al[4][4];
        #pragma unroll
        for (int i = 0; i < 4; i++) {
            uint32_t off = (uint32_t)((wm + i * 16 + a_row) * RP + kb + a_kh8) * 2;
            ldsm_x4(sQh_b + off, ah[i][0], ah[i][1], ah[i][2], ah[i][3]);
            ldsm_x4(sQl_b + off, al[i][0], al[i][1], al[i][2], al[i][3]);
        }
        #pragma unroll
        for (int j = 0; j < 4; j++) {
            uint32_t off = (uint32_t)((wn + j * 8 + b_row) * RP + kb + b_kh8) * 2;
            uint32_t bh2[2], bl2[2];
            ldsm_x2(sKh_b + off, bh2[0], bh2[1]);
            ldsm_x2(sKl_b + off, bl2[0], bl2[1]);
            #pragma unroll
            for (int i = 0; i < 4; i++) {
                mma_bf16(acc[i][j], ah[i], bh2);
                mma_bf16(acc[i][j], ah[i], bl2);
                mma_bf16(acc[i][j], al[i], bh2);
            }
        }
    }

    const float scale = 1.0f / 16.0f;     // 1/(2*sqrt(dk)), folds entmax z = s/2
    int r0 = lane >> 2;
    int cp = (lane & 3) * 2;
    #pragma unroll
    for (int i = 0; i < 4; i++) {
        int grow0 = qt * 128 + wm + i * 16 + r0;
        #pragma unroll
        for (int j = 0; j < 4; j++) {
            int gcol = kt * 256 + wn + j * 8 + cp;
            float2 v0 = make_float2(acc[i][j][0] * scale, acc[i][j][1] * scale);
            float2 v1 = make_float2(acc[i][j][2] * scale, acc[i][j][3] * scale);
            *(float2*)(g_s + ((size_t)bh * L + grow0) * L + gcol) = v0;
            *(float2*)(g_s + ((size_t)bh * L + grow0 + 8) * L + gcol) = v1;
        }
    }
}

// ---------------------------------------------------------------------------
// Phase 3: entmax-1.5, one WARP per (b,q) row; shuffle-only Newton.
// cp.async double buffer: lane prefetches head h+1's 48 floats (its own
// private smem slots) while Newton runs on head h. No barriers needed.
// ---------------------------------------------------------------------------
#define EM_SM_BYTES (4 * 2 * 1536 * 4)     // 4 warps x 2 bufs x 1536 floats

__global__ void __launch_bounds__(128) entmax_warp_kernel(
    const int* __restrict__ mask, float* __restrict__ out)
{
    extern __shared__ float zs[];

    int w = threadIdx.x >> 5, lane = threadIdx.x & 31;
    int warpg = blockIdx.x * 4 + w;
    int b = warpg / L, qi = warpg % L;

    float* wbuf = zs + w * 2 * 1536;
    uint32_t wbuf_u = smem_u32(wbuf);

    // validity bitmask: bit (i*4+j) <-> column 4*(lane + i*32) + j
    unsigned long long vbits = 0ull;
    {
        const int4* mrow = (const int4*)(mask + b * L);
        #pragma unroll
        for (int i = 0; i < 12; i++) {
            int4 mv = mrow[lane + i * 32];
            if (mv.x) vbits |= 1ull << (i * 4 + 0);
            if (mv.y) vbits |= 1ull << (i * 4 + 1);
            if (mv.z) vbits |= 1ull << (i * 4 + 2);
            if (mv.w) vbits |= 1ull << (i * 4 + 3);
        }
    }

    float acc[48];
    #pragma unroll
    for (int e = 0; e < 48; e++) acc[e] = 0.f;

    const float invH = 1.0f / 12.0f;
    const size_t rowstride = (size_t)L * L;      // per-head stride
    const float* rows0 = g_s + ((size_t)b * H * L + qi) * L;

    auto issue = [&](int h, int bufi) {
        const float4* src = (const float4*)(rows0 + (size_t)h * rowstride);
        uint32_t dst = wbuf_u + (uint32_t)bufi * 1536 * 4;
        #pragma unroll
        for (int i = 0; i < 12; i++) {
            int f4 = lane + i * 32;
            cpa16(dst + (uint32_t)f4 * 16, src + f4);
        }
        CPA_COMMIT();
    };

    issue(0, 0);

    for (int h = 0; h < H; h++) {
        if (h < H - 1) { issue(h + 1, (h + 1) & 1); CPA_WAIT1(); }
        else           { CPA_WAIT0(); }

        const float* zbuf = wbuf + (h & 1) * 1536;
        float z[48];
        float m = -1e30f;
        #pragma unroll
        for (int i = 0; i < 12; i++) {
            float4 v = *(const float4*)(zbuf + (lane + i * 32) * 4);
            z[i * 4 + 0] = (vbits >> (i * 4 + 0)) & 1 ? v.x : -1e30f;
            z[i * 4 + 1] = (vbits >> (i * 4 + 1)) & 1 ? v.y : -1e30f;
            z[i * 4 + 2] = (vbits >> (i * 4 + 2)) & 1 ? v.z : -1e30f;
            z[i * 4 + 3] = (vbits >> (i * 4 + 3)) & 1 ? v.w : -1e30f;
            m = fmaxf(m, fmaxf(fmaxf(z[i * 4], z[i * 4 + 1]), fmaxf(z[i * 4 + 2], z[i * 4 + 3])));
        }
        #pragma unroll
        for (int o = 16; o; o >>= 1) m = fmaxf(m, __shfl_xor_sync(0xffffffffu, m, o));

        float tau = m - 1.0f;
        for (int it = 0; it < 24; it++) {
            float s0 = 0.f, s1 = 0.f;
            #pragma unroll
            for (int e = 0; e < 48; e++) {
                float d = z[e] - tau;
                if (d > 0.f) { s0 = fmaf(d, d, s0); s1 += d; }
            }
            #pragma unroll
            for (int o = 16; o; o >>= 1) {
                s0 += __shfl_xor_sync(0xffffffffu, s0, o);
                s1 += __shfl_xor_sync(0xffffffffu, s1, o);
            }
            if (s1 <= 0.f) break;
            float step = (s0 - 1.0f) / (2.0f * s1);
            tau += step;
            if (fabsf(step) <= 5e-7f) break;
        }

        #pragma unroll
        for (int e = 0; e < 48; e++) {
            float d = z[e] - tau;
            if (d > 0.f) acc[e] = fmaf(d * d, invH, acc[e]);
        }
    }

    float4* orow = (float4*)(out + ((size_t)b * L + qi) * L);
    #pragma unroll
    for (int i = 0; i < 12; i++) {
        float4 v;
        v.x = acc[i * 4 + 0]; v.y = acc[i * 4 + 1];
        v.z = acc[i * 4 + 2]; v.w = acc[i * 4 + 3];
        orow[lane + i * 32] = v;
    }
}

// ---------------------------------------------------------------------------
extern "C" void kernel_launch(void* const* d_in, const int* in_sizes, int n_in,
                              void* d_out, int out_size)
{
    const float* query = (const float*)d_in[0];
    const float* key   = (const float*)d_in[1];
    const int*   mask  = (const int*)d_in[2];
    const float* wq_w  = (const float*)d_in[3];
    const float* wq_b  = (const float*)d_in[4];
    const float* wk_w  = (const float*)d_in[5];
    const float* wk_b  = (const float*)d_in[6];
    float* out = (float*)d_out;

    (void)in_sizes; (void)n_in; (void)out_size;

    cudaFuncSetAttribute(proj_mma_kernel,
                         cudaFuncAttributeMaxDynamicSharedMemorySize, PROJ_SM_BYTES);
    cudaFuncSetAttribute(scores_mma_kernel,
                         cudaFuncAttributeMaxDynamicSharedMemorySize, SC_SM_BYTES);
    cudaFuncSetAttribute(entmax_warp_kernel,
                         cudaFuncAttributeMaxDynamicSharedMemorySize, EM_SM_BYTES);

    {
        int n4_x = (int)(BLD / 4);
        int n4_w = (int)(DD / 4);
        split_src_kernel<<<(n4_x + 255) / 256, 256>>>(query, 0, n4_x);
        split_src_kernel<<<(n4_x + 255) / 256, 256>>>(key,   1, n4_x);
        split_src_kernel<<<(n4_w + 255) / 256, 256>>>(wq_w,  2, n4_w);
        split_src_kernel<<<(n4_w + 255) / 256, 256>>>(wk_w,  3, n4_w);
    }

    dim3 pgrid(D / 256, (B * L) / 128, 2);       // (3, 24, 2)
    proj_mma_kernel<<<pgrid, 512, PROJ_SM_BYTES>>>(wq_b, wk_b);

    dim3 sgrid(L / 256, L / 128, B * H);         // (6, 12, 24)
    scores_mma_kernel<<<sgrid, 512, SC_SM_BYTES>>>();

    entmax_warp_kernel<<<(B * L) / 4, 128, EM_SM_BYTES>>>(mask, out);
}

// round 7
// speedup vs baseline: 1.6471x; 1.0583x over previous
#include <cuda_runtime.h>
#include <cuda_bf16.h>
#include <cstdint>

#define B 2
#define L 1536
#define D 768
#define H 12
#define DK 64
#define BLD ((size_t)B * L * D)
#define DD  ((size_t)D * D)

// ---------------------------------------------------------------------------
// Scratch (allocation-free rule: static __device__ arrays)
// ---------------------------------------------------------------------------
__device__ __nv_bfloat16 g_xqh[BLD], g_xql[BLD];
__device__ __nv_bfloat16 g_xkh[BLD], g_xkl[BLD];
__device__ __nv_bfloat16 g_wqh[DD],  g_wql[DD];
__device__ __nv_bfloat16 g_wkh[DD],  g_wkl[DD];
__device__ __nv_bfloat16 g_qh[BLD], g_ql[BLD];
__device__ __nv_bfloat16 g_kh[BLD], g_kl[BLD];
__device__ float g_s[(size_t)B * H * L * L];                // 226.5 MB

__device__ __forceinline__ uint32_t smem_u32(const void* p) {
    uint32_t a;
    asm("{ .reg .u64 t; cvta.to.shared.u64 t, %1; cvt.u32.u64 %0, t; }" : "=r"(a) : "l"(p));
    return a;
}
__device__ __forceinline__ void ldsm_x4(uint32_t addr, uint32_t& r0, uint32_t& r1,
                                        uint32_t& r2, uint32_t& r3) {
    asm volatile("ldmatrix.sync.aligned.m8n8.x4.shared.b16 {%0,%1,%2,%3}, [%4];"
                 : "=r"(r0), "=r"(r1), "=r"(r2), "=r"(r3) : "r"(addr));
}
__device__ __forceinline__ void ldsm_x2(uint32_t addr, uint32_t& r0, uint32_t& r1) {
    asm volatile("ldmatrix.sync.aligned.m8n8.x2.shared.b16 {%0,%1}, [%2];"
                 : "=r"(r0), "=r"(r1) : "r"(addr));
}
__device__ __forceinline__ void mma_bf16(float* c, const uint32_t* a, const uint32_t* b) {
    asm volatile(
        "mma.sync.aligned.m16n8k16.row.col.f32.bf16.bf16.f32 "
        "{%0,%1,%2,%3}, {%4,%5,%6,%7}, {%8,%9}, {%0,%1,%2,%3};"
        : "+f"(c[0]), "+f"(c[1]), "+f"(c[2]), "+f"(c[3])
        : "r"(a[0]), "r"(a[1]), "r"(a[2]), "r"(a[3]), "r"(b[0]), "r"(b[1]));
}
__device__ __forceinline__ void cpa16(uint32_t s, const void* g) {
    asm volatile("cp.async.cg.shared.global [%0], [%1], 16;" :: "r"(s), "l"(g));
}
#define CPA_COMMIT() asm volatile("cp.async.commit_group;" ::: "memory")
#define CPA_WAIT1()  asm volatile("cp.async.wait_group 1;" ::: "memory")
#define CPA_WAIT0()  asm volatile("cp.async.wait_group 0;" ::: "memory")

// ---------------------------------------------------------------------------
// Phase 0: fp32 -> bf16 hi/lo split of ALL four sources, ONE launch.
// Region layout (in float4 units): [0,n4x) query, [n4x,2n4x) key,
// [2n4x, 2n4x+n4w) wq_w, [2n4x+n4w, 2n4x+2n4w) wk_w.
// ---------------------------------------------------------------------------
__global__ void split_all_kernel(const float* __restrict__ query,
                                 const float* __restrict__ key,
                                 const float* __restrict__ wq,
                                 const float* __restrict__ wk)
{
    const int n4x = (int)(BLD / 4);
    const int n4w = (int)(DD / 4);
    int i = blockIdx.x * blockDim.x + threadIdx.x;

    const float* src;
    __nv_bfloat16 *dh, *dl;
    int li;
    if (i < 2 * n4x) {
        if (i < n4x) { src = query; dh = g_xqh; dl = g_xql; li = i; }
        else         { src = key;   dh = g_xkh; dl = g_xkl; li = i - n4x; }
    } else {
        int j = i - 2 * n4x;
        if (j >= 2 * n4w) return;
        if (j < n4w) { src = wq; dh = g_wqh; dl = g_wql; li = j; }
        else         { src = wk; dh = g_wkh; dl = g_wkl; li = j - n4w; }
    }

    float4 v = ((const float4*)src)[li];
    __nv_bfloat16 h[4], l[4];
    const float* f = &v.x;
    #pragma unroll
    for (int j = 0; j < 4; j++) {
        h[j] = __float2bfloat16(f[j]);
        l[j] = __float2bfloat16(f[j] - __bfloat162float(h[j]));
    }
    ((uint2*)dh)[li] = *(uint2*)h;
    ((uint2*)dl)[li] = *(uint2*)l;
}

// ---------------------------------------------------------------------------
// Phase 1: projection via HMMA bf16x3, cp.async double-buffered K loop.
// CTA tile 128(M) x 256(N), 512 thr, K chunks of 64, 2 smem buffers.
// ---------------------------------------------------------------------------
#define RP 72
#define P_AH 0
#define P_AL (128 * RP)
#define P_BH (2 * 128 * RP)
#define P_BL (2 * 128 * RP + 256 * RP)
#define PROJ_BUF (2 * 128 * RP + 2 * 256 * RP)
#define PROJ_SM_BYTES (2 * PROJ_BUF * 2)

__global__ void __launch_bounds__(512, 1) proj_mma_kernel(
    const float* __restrict__ biasq, const float* __restrict__ biask)
{
    extern __shared__ __nv_bfloat16 sm[];
    const uint32_t sm_b = smem_u32(sm);

    int nt = blockIdx.x, mt = blockIdx.y, which = blockIdx.z;
    int tid = threadIdx.x;
    int wid = tid >> 5, lane = tid & 31;

    const __nv_bfloat16* xh = which ? g_xkh : g_xqh;
    const __nv_bfloat16* xl = which ? g_xkl : g_xql;
    const __nv_bfloat16* wh = which ? g_wkh : g_wqh;
    const __nv_bfloat16* wl = which ? g_wkl : g_wql;
    __nv_bfloat16* oh = which ? g_kh : g_qh;
    __nv_bfloat16* ol = which ? g_kl : g_ql;
    const float* bias = which ? biask : biasq;

    int wm = (wid & 1) * 64;
    int wn = (wid >> 1) * 32;

    float acc[4][4][4];
    #pragma unroll
    for (int i = 0; i < 4; i++)
        #pragma unroll
        for (int j = 0; j < 4; j++)
            #pragma unroll
            for (int r = 0; r < 4; r++) acc[i][j][r] = 0.f;

    int a_row = lane & 15;
    int a_kh8 = (lane >> 4) * 8;
    int b_row = lane & 7;
    int b_kh8 = ((lane >> 3) & 1) * 8;

    int lrowA[2], lc8A[2], lrowB[4], lc8B[4];
    #pragma unroll
    for (int it = 0; it < 2; it++) { int idx = tid + it * 512; lrowA[it] = idx >> 3; lc8A[it] = (idx & 7) * 8; }
    #pragma unroll
    for (int it = 0; it < 4; it++) { int idx = tid + it * 512; lrowB[it] = idx >> 3; lc8B[it] = (idx & 7) * 8; }

    auto prefetch = [&](int kc, int pb) {
        uint32_t base = sm_b + (uint32_t)pb * PROJ_BUF * 2;
        #pragma unroll
        for (int it = 0; it < 2; it++) {
            size_t g = (size_t)(mt * 128 + lrowA[it]) * D + kc + lc8A[it];
            uint32_t so = (uint32_t)(lrowA[it] * RP + lc8A[it]) * 2;
            cpa16(base + P_AH * 2 + so, xh + g);
            cpa16(base + P_AL * 2 + so, xl + g);
        }
        #pragma unroll
        for (int it = 0; it < 4; it++) {
            size_t g = (size_t)(nt * 256 + lrowB[it]) * D + kc + lc8B[it];
            uint32_t so = (uint32_t)(lrowB[it] * RP + lc8B[it]) * 2;
            cpa16(base + P_BH * 2 + so, wh + g);
            cpa16(base + P_BL * 2 + so, wl + g);
        }
        CPA_COMMIT();
    };

    prefetch(0, 0);

    int buf = 0;
    for (int kci = 0; kci < 12; kci++) {
        if (kci < 11) { prefetch((kci + 1) * 64, buf ^ 1); CPA_WAIT1(); }
        else          { CPA_WAIT0(); }
        __syncthreads();

        uint32_t base = sm_b + (uint32_t)buf * PROJ_BUF * 2;
        uint32_t sAh_b = base + P_AH * 2, sAl_b = base + P_AL * 2;
        uint32_t sBh_b = base + P_BH * 2, sBl_b = base + P_BL * 2;

        #pragma unroll
        for (int ks = 0; ks < 4; ks++) {
            int kb = ks * 16;
            uint32_t ah[4][4], al[4][4];
            #pragma unroll
            for (int i = 0; i < 4; i++) {
                uint32_t off = (uint32_t)((wm + i * 16 + a_row) * RP + kb + a_kh8) * 2;
                ldsm_x4(sAh_b + off, ah[i][0], ah[i][1], ah[i][2], ah[i][3]);
                ldsm_x4(sAl_b + off, al[i][0], al[i][1], al[i][2], al[i][3]);
            }
            #pragma unroll
            for (int j = 0; j < 4; j++) {
                uint32_t off = (uint32_t)((wn + j * 8 + b_row) * RP + kb + b_kh8) * 2;
                uint32_t bh[2], bl[2];
                ldsm_x2(sBh_b + off, bh[0], bh[1]);
                ldsm_x2(sBl_b + off, bl[0], bl[1]);
                #pragma unroll
                for (int i = 0; i < 4; i++) {
                    mma_bf16(acc[i][j], ah[i], bh);
                    mma_bf16(acc[i][j], ah[i], bl);
                    mma_bf16(acc[i][j], al[i], bh);
                }
            }
        }
        __syncthreads();
        buf ^= 1;
    }

    int r0 = lane >> 2;
    int cp = (lane & 3) * 2;
    #pragma unroll
    for (int i = 0; i < 4; i++) {
        int grow0 = mt * 128 + wm + i * 16 + r0;
        #pragma unroll
        for (int j = 0; j < 4; j++) {
            int gcol = nt * 256 + wn + j * 8 + cp;
            float2 bv = *(const float2*)(bias + gcol);
            #pragma unroll
            for (int half = 0; half < 2; half++) {
                float v0 = acc[i][j][half * 2 + 0] + bv.x;
                float v1 = acc[i][j][half * 2 + 1] + bv.y;
                __nv_bfloat16 h0 = __float2bfloat16(v0);
                __nv_bfloat16 h1 = __float2bfloat16(v1);
                __nv_bfloat16 l0 = __float2bfloat16(v0 - __bfloat162float(h0));
                __nv_bfloat16 l1 = __float2bfloat16(v1 - __bfloat162float(h1));
                size_t addr = (size_t)(grow0 + half * 8) * D + gcol;
                __nv_bfloat16 hp[2] = {h0, h1}, lp[2] = {l0, l1};
                *(uint32_t*)(oh + addr) = *(uint32_t*)hp;
                *(uint32_t*)(ol + addr) = *(uint32_t*)lp;
            }
        }
    }
}

// ---------------------------------------------------------------------------
// Phase 2: scores via HMMA bf16x3 (R4 version).
// CTA tile 128(q) x 256(k) x 64(dk), 512 thr. grid (6 kt, 12 qt, 24 bh)
// ---------------------------------------------------------------------------
#define SC_SM_Q (128 * RP)
#define SC_SM_K (256 * RP)
#define SC_SM_BYTES ((2 * SC_SM_Q + 2 * SC_SM_K) * 2)

__global__ void __launch_bounds__(512, 1) scores_mma_kernel()
{
    extern __shared__ __nv_bfloat16 sm[];
    __nv_bfloat16* sQh = sm;
    __nv_bfloat16* sQl = sm + SC_SM_Q;
    __nv_bfloat16* sKh = sm + 2 * SC_SM_Q;
    __nv_bfloat16* sKl = sm + 2 * SC_SM_Q + SC_SM_K;

    int kt = blockIdx.x, qt = blockIdx.y, bh = blockIdx.z;
    int b = bh / H, h = bh % H;
    int tid = threadIdx.x;
    int wid = tid >> 5, lane = tid & 31;

    {
        const __nv_bfloat16* qhb = g_qh + (size_t)(b * L + qt * 128) * D + h * DK;
        const __nv_bfloat16* qlb = g_ql + (size_t)(b * L + qt * 128) * D + h * DK;
        const __nv_bfloat16* khb = g_kh + (size_t)(b * L + kt * 256) * D + h * DK;
        const __nv_bfloat16* klb = g_kl + (size_t)(b * L + kt * 256) * D + h * DK;

        #pragma unroll
        for (int it = 0; it < 2; it++) {
            int idx = tid + it * 512;
            int row = idx >> 3;
            int c8  = (idx & 7) * 8;
            *(uint4*)(sQh + row * RP + c8) = *(const uint4*)(qhb + (size_t)row * D + c8);
            *(uint4*)(sQl + row * RP + c8) = *(const uint4*)(qlb + (size_t)row * D + c8);
        }
        #pragma unroll
        for (int it = 0; it < 4; it++) {
            int idx = tid + it * 512;
            int row = idx >> 3;
            int c8  = (idx & 7) * 8;
            *(uint4*)(sKh + row * RP + c8) = *(const uint4*)(khb + (size_t)row * D + c8);
            *(uint4*)(sKl + row * RP + c8) = *(const uint4*)(klb + (size_t)row * D + c8);
        }
    }
    __syncthreads();

    int wm = (wid & 1) * 64;
    int wn = (wid >> 1) * 32;

    float acc[4][4][4];
    #pragma unroll
    for (int i = 0; i < 4; i++)
        #pragma unroll
        for (int j = 0; j < 4; j++)
            #pragma unroll
            for (int r = 0; r < 4; r++) acc[i][j][r] = 0.f;

    uint32_t sQh_b = smem_u32(sQh), sQl_b = smem_u32(sQl);
    uint32_t sKh_b = smem_u32(sKh), sKl_b = smem_u32(sKl);

    int a_row = lane & 15;
    int a_kh8 = (lane >> 4) * 8;
    int b_row = lane & 7;
    int b_kh8 = ((lane >> 3) & 1) * 8;

    #pragma unroll
    for (int ks = 0; ks < 4; ks++) {
        int kb = ks * 16;
        uint32_t ah[4][4], al[4][4];
        #pragma unroll
        for (int i = 0; i < 4; i++) {
            uint32_t off = (uint32_t)((wm + i * 16 + a_row) * RP + kb + a_kh8) * 2;
            ldsm_x4(sQh_b + off, ah[i][0], ah[i][1], ah[i][2], ah[i][3]);
            ldsm_x4(sQl_b + off, al[i][0], al[i][1], al[i][2], al[i][3]);
        }
        #pragma unroll
        for (int j = 0; j < 4; j++) {
            uint32_t off = (uint32_t)((wn + j * 8 + b_row) * RP + kb + b_kh8) * 2;
            uint32_t bh2[2], bl2[2];
            ldsm_x2(sKh_b + off, bh2[0], bh2[1]);
            ldsm_x2(sKl_b + off, bl2[0], bl2[1]);
            #pragma unroll
            for (int i = 0; i < 4; i++) {
                mma_bf16(acc[i][j], ah[i], bh2);
                mma_bf16(acc[i][j], ah[i], bl2);
                mma_bf16(acc[i][j], al[i], bh2);
            }
        }
    }

    const float scale = 1.0f / 16.0f;
    int r0 = lane >> 2;
    int cp = (lane & 3) * 2;
    #pragma unroll
    for (int i = 0; i < 4; i++) {
        int grow0 = qt * 128 + wm + i * 16 + r0;
        #pragma unroll
        for (int j = 0; j < 4; j++) {
            int gcol = kt * 256 + wn + j * 8 + cp;
            float2 v0 = make_float2(acc[i][j][0] * scale, acc[i][j][1] * scale);
            float2 v1 = make_float2(acc[i][j][2] * scale, acc[i][j][3] * scale);
            *(float2*)(g_s + ((size_t)bh * L + grow0) * L + gcol) = v0;
            *(float2*)(g_s + ((size_t)bh * L + grow0 + 8) * L + gcol) = v1;
        }
    }
}

// ---------------------------------------------------------------------------
// Phase 3: entmax-1.5, one WARP per (b,q) row (R4 version: __ldg, no smem).
// ---------------------------------------------------------------------------
__global__ void __launch_bounds__(128) entmax_warp_kernel(
    const int* __restrict__ mask, float* __restrict__ out)
{
    int warp = (blockIdx.x * blockDim.x + threadIdx.x) >> 5;
    int lane = threadIdx.x & 31;
    int b = warp / L, qi = warp % L;

    unsigned long long vbits = 0ull;
    {
        const int4* mrow = (const int4*)(mask + b * L);
        #pragma unroll
        for (int i = 0; i < 12; i++) {
            int4 mv = mrow[lane + i * 32];
            if (mv.x) vbits |= 1ull << (i * 4 + 0);
            if (mv.y) vbits |= 1ull << (i * 4 + 1);
            if (mv.z) vbits |= 1ull << (i * 4 + 2);
            if (mv.w) vbits |= 1ull << (i * 4 + 3);
        }
    }

    float acc[48];
    #pragma unroll
    for (int e = 0; e < 48; e++) acc[e] = 0.f;

    const float invH = 1.0f / 12.0f;

    for (int h = 0; h < H; h++) {
        const float4* row = (const float4*)(g_s + ((size_t)(b * H + h) * L + qi) * L);
        float z[48];
        float m = -1e30f;
        #pragma unroll
        for (int i = 0; i < 12; i++) {
            float4 v = __ldg(row + lane + i * 32);
            z[i * 4 + 0] = (vbits >> (i * 4 + 0)) & 1 ? v.x : -1e30f;
            z[i * 4 + 1] = (vbits >> (i * 4 + 1)) & 1 ? v.y : -1e30f;
            z[i * 4 + 2] = (vbits >> (i * 4 + 2)) & 1 ? v.z : -1e30f;
            z[i * 4 + 3] = (vbits >> (i * 4 + 3)) & 1 ? v.w : -1e30f;
            m = fmaxf(m, fmaxf(fmaxf(z[i * 4], z[i * 4 + 1]), fmaxf(z[i * 4 + 2], z[i * 4 + 3])));
        }
        #pragma unroll
        for (int o = 16; o; o >>= 1) m = fmaxf(m, __shfl_xor_sync(0xffffffffu, m, o));

        float tau = m - 1.0f;

        for (int it = 0; it < 24; it++) {
            float s0 = 0.f, s1 = 0.f;
            #pragma unroll
            for (int e = 0; e < 48; e++) {
                float d = z[e] - tau;
                if (d > 0.f) { s0 = fmaf(d, d, s0); s1 += d; }
            }
            #pragma unroll
            for (int o = 16; o; o >>= 1) {
                s0 += __shfl_xor_sync(0xffffffffu, s0, o);
                s1 += __shfl_xor_sync(0xffffffffu, s1, o);
            }
            if (s1 <= 0.f) break;
            float step = (s0 - 1.0f) / (2.0f * s1);
            tau += step;
            if (fabsf(step) <= 5e-7f) break;
        }

        #pragma unroll
        for (int e = 0; e < 48; e++) {
            float d = z[e] - tau;
            if (d > 0.f) acc[e] = fmaf(d * d, invH, acc[e]);
        }
    }

    float4* orow = (float4*)(out + ((size_t)b * L + qi) * L);
    #pragma unroll
    for (int i = 0; i < 12; i++) {
        float4 v;
        v.x = acc[i * 4 + 0]; v.y = acc[i * 4 + 1];
        v.z = acc[i * 4 + 2]; v.w = acc[i * 4 + 3];
        orow[lane + i * 32] = v;
    }
}

// ---------------------------------------------------------------------------
extern "C" void kernel_launch(void* const* d_in, const int* in_sizes, int n_in,
                              void* d_out, int out_size)
{
    const float* query = (const float*)d_in[0];
    const float* key   = (const float*)d_in[1];
    const int*   mask  = (const int*)d_in[2];
    const float* wq_w  = (const float*)d_in[3];
    const float* wq_b  = (const float*)d_in[4];
    const float* wk_w  = (const float*)d_in[5];
    const float* wk_b  = (const float*)d_in[6];
    float* out = (float*)d_out;

    (void)in_sizes; (void)n_in; (void)out_size;

    cudaFuncSetAttribute(proj_mma_kernel,
                         cudaFuncAttributeMaxDynamicSharedMemorySize, PROJ_SM_BYTES);
    cudaFuncSetAttribute(scores_mma_kernel,
                         cudaFuncAttributeMaxDynamicSharedMemorySize, SC_SM_BYTES);

    {
        int total4 = (int)(2 * (BLD / 4) + 2 * (DD / 4));
        split_all_kernel<<<(total4 + 255) / 256, 256>>>(query, key, wq_w, wk_w);
    }

    dim3 pgrid(D / 256, (B * L) / 128, 2);       // (3, 24, 2)
    proj_mma_kernel<<<pgrid, 512, PROJ_SM_BYTES>>>(wq_b, wk_b);

    dim3 sgrid(L / 256, L / 128, B * H);         // (6, 12, 24)
    scores_mma_kernel<<<sgrid, 512, SC_SM_BYTES>>>();

    // launch index 3 (0-based) — ncu captures this one
    entmax_warp_kernel<<<(B * L) / 4, 128>>>(mask, out);
}

// round 8
// speedup vs baseline: 1.8081x; 1.0978x over previous
#include <cuda_runtime.h>
#include <cuda_bf16.h>
#include <cstdint>

#define B 2
#define L 1536
#define D 768
#define H 12
#define DK 64
#define BLD ((size_t)B * L * D)
#define DD  ((size_t)D * D)

// ---------------------------------------------------------------------------
// Scratch (allocation-free rule: static __device__ arrays)
// ---------------------------------------------------------------------------
__device__ __nv_bfloat16 g_xqh[BLD], g_xql[BLD];
__device__ __nv_bfloat16 g_xkh[BLD], g_xkl[BLD];
__device__ __nv_bfloat16 g_wqh[DD],  g_wql[DD];
__device__ __nv_bfloat16 g_wkh[DD],  g_wkl[DD];
__device__ __nv_bfloat16 g_qh[BLD], g_ql[BLD];
__device__ __nv_bfloat16 g_kh[BLD], g_kl[BLD];
__device__ float g_s[(size_t)B * H * L * L];                // 226.5 MB

__device__ __forceinline__ uint32_t smem_u32(const void* p) {
    uint32_t a;
    asm("{ .reg .u64 t; cvta.to.shared.u64 t, %1; cvt.u32.u64 %0, t; }" : "=r"(a) : "l"(p));
    return a;
}
__device__ __forceinline__ void ldsm_x4(uint32_t addr, uint32_t& r0, uint32_t& r1,
                                        uint32_t& r2, uint32_t& r3) {
    asm volatile("ldmatrix.sync.aligned.m8n8.x4.shared.b16 {%0,%1,%2,%3}, [%4];"
                 : "=r"(r0), "=r"(r1), "=r"(r2), "=r"(r3) : "r"(addr));
}
__device__ __forceinline__ void ldsm_x2(uint32_t addr, uint32_t& r0, uint32_t& r1) {
    asm volatile("ldmatrix.sync.aligned.m8n8.x2.shared.b16 {%0,%1}, [%2];"
                 : "=r"(r0), "=r"(r1) : "r"(addr));
}
__device__ __forceinline__ void mma_bf16(float* c, const uint32_t* a, const uint32_t* b) {
    asm volatile(
        "mma.sync.aligned.m16n8k16.row.col.f32.bf16.bf16.f32 "
        "{%0,%1,%2,%3}, {%4,%5,%6,%7}, {%8,%9}, {%0,%1,%2,%3};"
        : "+f"(c[0]), "+f"(c[1]), "+f"(c[2]), "+f"(c[3])
        : "r"(a[0]), "r"(a[1]), "r"(a[2]), "r"(a[3]), "r"(b[0]), "r"(b[1]));
}
__device__ __forceinline__ void cpa16(uint32_t s, const void* g) {
    asm volatile("cp.async.cg.shared.global [%0], [%1], 16;" :: "r"(s), "l"(g));
}
#define CPA_COMMIT() asm volatile("cp.async.commit_group;" ::: "memory")
#define CPA_WAIT1()  asm volatile("cp.async.wait_group 1;" ::: "memory")
#define CPA_WAIT0()  asm volatile("cp.async.wait_group 0;" ::: "memory")

// ---------------------------------------------------------------------------
// Phase 0: fp32 -> bf16 hi/lo split of ALL four sources, ONE launch.
// ---------------------------------------------------------------------------
__global__ void split_all_kernel(const float* __restrict__ query,
                                 const float* __restrict__ key,
                                 const float* __restrict__ wq,
                                 const float* __restrict__ wk)
{
    const int n4x = (int)(BLD / 4);
    const int n4w = (int)(DD / 4);
    int i = blockIdx.x * blockDim.x + threadIdx.x;

    const float* src;
    __nv_bfloat16 *dh, *dl;
    int li;
    if (i < 2 * n4x) {
        if (i < n4x) { src = query; dh = g_xqh; dl = g_xql; li = i; }
        else         { src = key;   dh = g_xkh; dl = g_xkl; li = i - n4x; }
    } else {
        int j = i - 2 * n4x;
        if (j >= 2 * n4w) return;
        if (j < n4w) { src = wq; dh = g_wqh; dl = g_wql; li = j; }
        else         { src = wk; dh = g_wkh; dl = g_wkl; li = j - n4w; }
    }

    float4 v = ((const float4*)src)[li];
    __nv_bfloat16 h[4], l[4];
    const float* f = &v.x;
    #pragma unroll
    for (int j = 0; j < 4; j++) {
        h[j] = __float2bfloat16(f[j]);
        l[j] = __float2bfloat16(f[j] - __bfloat162float(h[j]));
    }
    ((uint2*)dh)[li] = *(uint2*)h;
    ((uint2*)dl)[li] = *(uint2*)l;
}

// ---------------------------------------------------------------------------
// Phase 1: projection via HMMA bf16x3, cp.async double-buffered K loop.
// ---------------------------------------------------------------------------
#define RP 72
#define P_AH 0
#define P_AL (128 * RP)
#define P_BH (2 * 128 * RP)
#define P_BL (2 * 128 * RP + 256 * RP)
#define PROJ_BUF (2 * 128 * RP + 2 * 256 * RP)
#define PROJ_SM_BYTES (2 * PROJ_BUF * 2)

__global__ void __launch_bounds__(512, 1) proj_mma_kernel(
    const float* __restrict__ biasq, const float* __restrict__ biask)
{
    extern __shared__ __nv_bfloat16 sm[];
    const uint32_t sm_b = smem_u32(sm);

    int nt = blockIdx.x, mt = blockIdx.y, which = blockIdx.z;
    int tid = threadIdx.x;
    int wid = tid >> 5, lane = tid & 31;

    const __nv_bfloat16* xh = which ? g_xkh : g_xqh;
    const __nv_bfloat16* xl = which ? g_xkl : g_xql;
    const __nv_bfloat16* wh = which ? g_wkh : g_wqh;
    const __nv_bfloat16* wl = which ? g_wkl : g_wql;
    __nv_bfloat16* oh = which ? g_kh : g_qh;
    __nv_bfloat16* ol = which ? g_kl : g_ql;
    const float* bias = which ? biask : biasq;

    int wm = (wid & 1) * 64;
    int wn = (wid >> 1) * 32;

    float acc[4][4][4];
    #pragma unroll
    for (int i = 0; i < 4; i++)
        #pragma unroll
        for (int j = 0; j < 4; j++)
            #pragma unroll
            for (int r = 0; r < 4; r++) acc[i][j][r] = 0.f;

    int a_row = lane & 15;
    int a_kh8 = (lane >> 4) * 8;
    int b_row = lane & 7;
    int b_kh8 = ((lane >> 3) & 1) * 8;

    int lrowA[2], lc8A[2], lrowB[4], lc8B[4];
    #pragma unroll
    for (int it = 0; it < 2; it++) { int idx = tid + it * 512; lrowA[it] = idx >> 3; lc8A[it] = (idx & 7) * 8; }
    #pragma unroll
    for (int it = 0; it < 4; it++) { int idx = tid + it * 512; lrowB[it] = idx >> 3; lc8B[it] = (idx & 7) * 8; }

    auto prefetch = [&](int kc, int pb) {
        uint32_t base = sm_b + (uint32_t)pb * PROJ_BUF * 2;
        #pragma unroll
        for (int it = 0; it < 2; it++) {
            size_t g = (size_t)(mt * 128 + lrowA[it]) * D + kc + lc8A[it];
            uint32_t so = (uint32_t)(lrowA[it] * RP + lc8A[it]) * 2;
            cpa16(base + P_AH * 2 + so, xh + g);
            cpa16(base + P_AL * 2 + so, xl + g);
        }
        #pragma unroll
        for (int it = 0; it < 4; it++) {
            size_t g = (size_t)(nt * 256 + lrowB[it]) * D + kc + lc8B[it];
            uint32_t so = (uint32_t)(lrowB[it] * RP + lc8B[it]) * 2;
            cpa16(base + P_BH * 2 + so, wh + g);
            cpa16(base + P_BL * 2 + so, wl + g);
        }
        CPA_COMMIT();
    };

    prefetch(0, 0);

    int buf = 0;
    for (int kci = 0; kci < 12; kci++) {
        if (kci < 11) { prefetch((kci + 1) * 64, buf ^ 1); CPA_WAIT1(); }
        else          { CPA_WAIT0(); }
        __syncthreads();

        uint32_t base = sm_b + (uint32_t)buf * PROJ_BUF * 2;
        uint32_t sAh_b = base + P_AH * 2, sAl_b = base + P_AL * 2;
        uint32_t sBh_b = base + P_BH * 2, sBl_b = base + P_BL * 2;

        #pragma unroll
        for (int ks = 0; ks < 4; ks++) {
            int kb = ks * 16;
            uint32_t ah[4][4], al[4][4];
            #pragma unroll
            for (int i = 0; i < 4; i++) {
                uint32_t off = (uint32_t)((wm + i * 16 + a_row) * RP + kb + a_kh8) * 2;
                ldsm_x4(sAh_b + off, ah[i][0], ah[i][1], ah[i][2], ah[i][3]);
                ldsm_x4(sAl_b + off, al[i][0], al[i][1], al[i][2], al[i][3]);
            }
            #pragma unroll
            for (int j = 0; j < 4; j++) {
                uint32_t off = (uint32_t)((wn + j * 8 + b_row) * RP + kb + b_kh8) * 2;
                uint32_t bh[2], bl[2];
                ldsm_x2(sBh_b + off, bh[0], bh[1]);
                ldsm_x2(sBl_b + off, bl[0], bl[1]);
                #pragma unroll
                for (int i = 0; i < 4; i++) {
                    mma_bf16(acc[i][j], ah[i], bh);
                    mma_bf16(acc[i][j], ah[i], bl);
                    mma_bf16(acc[i][j], al[i], bh);
                }
            }
        }
        __syncthreads();
        buf ^= 1;
    }

    int r0 = lane >> 2;
    int cp = (lane & 3) * 2;
    #pragma unroll
    for (int i = 0; i < 4; i++) {
        int grow0 = mt * 128 + wm + i * 16 + r0;
        #pragma unroll
        for (int j = 0; j < 4; j++) {
            int gcol = nt * 256 + wn + j * 8 + cp;
            float2 bv = *(const float2*)(bias + gcol);
            #pragma unroll
            for (int half = 0; half < 2; half++) {
                float v0 = acc[i][j][half * 2 + 0] + bv.x;
                float v1 = acc[i][j][half * 2 + 1] + bv.y;
                __nv_bfloat16 h0 = __float2bfloat16(v0);
                __nv_bfloat16 h1 = __float2bfloat16(v1);
                __nv_bfloat16 l0 = __float2bfloat16(v0 - __bfloat162float(h0));
                __nv_bfloat16 l1 = __float2bfloat16(v1 - __bfloat162float(h1));
                size_t addr = (size_t)(grow0 + half * 8) * D + gcol;
                __nv_bfloat16 hp[2] = {h0, h1}, lp[2] = {l0, l1};
                *(uint32_t*)(oh + addr) = *(uint32_t*)hp;
                *(uint32_t*)(ol + addr) = *(uint32_t*)lp;
            }
        }
    }
}

// ---------------------------------------------------------------------------
// Phase 2: scores via HMMA bf16x3.
// ---------------------------------------------------------------------------
#define SC_SM_Q (128 * RP)
#define SC_SM_K (256 * RP)
#define SC_SM_BYTES ((2 * SC_SM_Q + 2 * SC_SM_K) * 2)

__global__ void __launch_bounds__(512, 1) scores_mma_kernel()
{
    extern __shared__ __nv_bfloat16 sm[];
    __nv_bfloat16* sQh = sm;
    __nv_bfloat16* sQl = sm + SC_SM_Q;
    __nv_bfloat16* sKh = sm + 2 * SC_SM_Q;
    __nv_bfloat16* sKl = sm + 2 * SC_SM_Q + SC_SM_K;

    int kt = blockIdx.x, qt = blockIdx.y, bh = blockIdx.z;
    int b = bh / H, h = bh % H;
    int tid = threadIdx.x;
    int wid = tid >> 5, lane = tid & 31;

    {
        const __nv_bfloat16* qhb = g_qh + (size_t)(b * L + qt * 128) * D + h * DK;
        const __nv_bfloat16* qlb = g_ql + (size_t)(b * L + qt * 128) * D + h * DK;
        const __nv_bfloat16* khb = g_kh + (size_t)(b * L + kt * 256) * D + h * DK;
        const __nv_bfloat16* klb = g_kl + (size_t)(b * L + kt * 256) * D + h * DK;

        #pragma unroll
        for (int it = 0; it < 2; it++) {
            int idx = tid + it * 512;
            int row = idx >> 3;
            int c8  = (idx & 7) * 8;
            *(uint4*)(sQh + row * RP + c8) = *(const uint4*)(qhb + (size_t)row * D + c8);
            *(uint4*)(sQl + row * RP + c8) = *(const uint4*)(qlb + (size_t)row * D + c8);
        }
        #pragma unroll
        for (int it = 0; it < 4; it++) {
            int idx = tid + it * 512;
            int row = idx >> 3;
            int c8  = (idx & 7) * 8;
            *(uint4*)(sKh + row * RP + c8) = *(const uint4*)(khb + (size_t)row * D + c8);
            *(uint4*)(sKl + row * RP + c8) = *(const uint4*)(klb + (size_t)row * D + c8);
        }
    }
    __syncthreads();

    int wm = (wid & 1) * 64;
    int wn = (wid >> 1) * 32;

    float acc[4][4][4];
    #pragma unroll
    for (int i = 0; i < 4; i++)
        #pragma unroll
        for (int j = 0; j < 4; j++)
            #pragma unroll
            for (int r = 0; r < 4; r++) acc[i][j][r] = 0.f;

    uint32_t sQh_b = smem_u32(sQh), sQl_b = smem_u32(sQl);
    uint32_t sKh_b = smem_u32(sKh), sKl_b = smem_u32(sKl);

    int a_row = lane & 15;
    int a_kh8 = (lane >> 4) * 8;
    int b_row = lane & 7;
    int b_kh8 = ((lane >> 3) & 1) * 8;

    #pragma unroll
    for (int ks = 0; ks < 4; ks++) {
        int kb = ks * 16;
        uint32_t ah[4][4], al[4][4];
        #pragma unroll
        for (int i = 0; i < 4; i++) {
            uint32_t off = (uint32_t)((wm + i * 16 + a_row) * RP + kb + a_kh8) * 2;
            ldsm_x4(sQh_b + off, ah[i][0], ah[i][1], ah[i][2], ah[i][3]);
            ldsm_x4(sQl_b + off, al[i][0], al[i][1], al[i][2], al[i][3]);
        }
        #pragma unroll
        for (int j = 0; j < 4; j++) {
            uint32_t off = (uint32_t)((wn + j * 8 + b_row) * RP + kb + b_kh8) * 2;
            uint32_t bh2[2], bl2[2];
            ldsm_x2(sKh_b + off, bh2[0], bh2[1]);
            ldsm_x2(sKl_b + off, bl2[0], bl2[1]);
            #pragma unroll
            for (int i = 0; i < 4; i++) {
                mma_bf16(acc[i][j], ah[i], bh2);
                mma_bf16(acc[i][j], ah[i], bl2);
                mma_bf16(acc[i][j], al[i], bh2);
            }
        }
    }

    const float scale = 1.0f / 16.0f;
    int r0 = lane >> 2;
    int cp = (lane & 3) * 2;
    #pragma unroll
    for (int i = 0; i < 4; i++) {
        int grow0 = qt * 128 + wm + i * 16 + r0;
        #pragma unroll
        for (int j = 0; j < 4; j++) {
            int gcol = kt * 256 + wn + j * 8 + cp;
            float2 v0 = make_float2(acc[i][j][0] * scale, acc[i][j][1] * scale);
            float2 v1 = make_float2(acc[i][j][2] * scale, acc[i][j][3] * scale);
            *(float2*)(g_s + ((size_t)bh * L + grow0) * L + gcol) = v0;
            *(float2*)(g_s + ((size_t)bh * L + grow0 + 8) * L + gcol) = v1;
        }
    }
}

// ---------------------------------------------------------------------------
// Phase 3: entmax-1.5, warp per row. Accelerated root-find:
// Newton on sqrt(f) while far (s0>2; sqrt(f) is ~linear far from the root),
// standard Newton near/after overshoot (globally convergent on convex f).
// ---------------------------------------------------------------------------
__global__ void __launch_bounds__(128) entmax_warp_kernel(
    const int* __restrict__ mask, float* __restrict__ out)
{
    int warp = (blockIdx.x * blockDim.x + threadIdx.x) >> 5;
    int lane = threadIdx.x & 31;
    int b = warp / L, qi = warp % L;

    unsigned long long vbits = 0ull;
    {
        const int4* mrow = (const int4*)(mask + b * L);
        #pragma unroll
        for (int i = 0; i < 12; i++) {
            int4 mv = mrow[lane + i * 32];
            if (mv.x) vbits |= 1ull << (i * 4 + 0);
            if (mv.y) vbits |= 1ull << (i * 4 + 1);
            if (mv.z) vbits |= 1ull << (i * 4 + 2);
            if (mv.w) vbits |= 1ull << (i * 4 + 3);
        }
    }

    float acc[48];
    #pragma unroll
    for (int e = 0; e < 48; e++) acc[e] = 0.f;

    const float invH = 1.0f / 12.0f;

    for (int h = 0; h < H; h++) {
        const float4* row = (const float4*)(g_s + ((size_t)(b * H + h) * L + qi) * L);
        float z[48];
        float m = -1e30f;
        #pragma unroll
        for (int i = 0; i < 12; i++) {
            float4 v = __ldg(row + lane + i * 32);
            z[i * 4 + 0] = (vbits >> (i * 4 + 0)) & 1 ? v.x : -1e30f;
            z[i * 4 + 1] = (vbits >> (i * 4 + 1)) & 1 ? v.y : -1e30f;
            z[i * 4 + 2] = (vbits >> (i * 4 + 2)) & 1 ? v.z : -1e30f;
            z[i * 4 + 3] = (vbits >> (i * 4 + 3)) & 1 ? v.w : -1e30f;
            m = fmaxf(m, fmaxf(fmaxf(z[i * 4], z[i * 4 + 1]), fmaxf(z[i * 4 + 2], z[i * 4 + 3])));
        }
        #pragma unroll
        for (int o = 16; o; o >>= 1) m = fmaxf(m, __shfl_xor_sync(0xffffffffu, m, o));

        float tau = m - 1.0f;        // f(tau0) >= 1 (root is to the right)
        const float tmax = m - 1e-7f;

        for (int it = 0; it < 20; it++) {
            float s0 = 0.f, s1 = 0.f;
            #pragma unroll
            for (int e = 0; e < 48; e++) {
                float d = fmaxf(z[e] - tau, 0.f);
                s1 += d;
                s0 = fmaf(d, d, s0);
            }
            #pragma unroll
            for (int o = 16; o; o >>= 1) {
                s0 += __shfl_xor_sync(0xffffffffu, s0, o);
                s1 += __shfl_xor_sync(0xffffffffu, s1, o);
            }
            float step;
            if (s0 > 2.0f) {
                // Newton on sqrt(f): tau += (s0 - sqrt(s0)) / s1
                step = (s0 - sqrtf(s0)) / s1;
            } else {
                // standard Newton on f (monotone-convergent on convex f)
                step = (s0 - 1.0f) / (2.0f * s1);
            }
            tau = fminf(tau + step, tmax);
            if (fabsf(step) <= 5e-7f) break;
        }

        #pragma unroll
        for (int e = 0; e < 48; e++) {
            float d = z[e] - tau;
            if (d > 0.f) acc[e] = fmaf(d * d, invH, acc[e]);
        }
    }

    float4* orow = (float4*)(out + ((size_t)b * L + qi) * L);
    #pragma unroll
    for (int i = 0; i < 12; i++) {
        float4 v;
        v.x = acc[i * 4 + 0]; v.y = acc[i * 4 + 1];
        v.z = acc[i * 4 + 2]; v.w = acc[i * 4 + 3];
        orow[lane + i * 32] = v;
    }
}

// ---------------------------------------------------------------------------
extern "C" void kernel_launch(void* const* d_in, const int* in_sizes, int n_in,
                              void* d_out, int out_size)
{
    const float* query = (const float*)d_in[0];
    const float* key   = (const float*)d_in[1];
    const int*   mask  = (const int*)d_in[2];
    const float* wq_w  = (const float*)d_in[3];
    const float* wq_b  = (const float*)d_in[4];
    const float* wk_w  = (const float*)d_in[5];
    const float* wk_b  = (const float*)d_in[6];
    float* out = (float*)d_out;

    (void)in_sizes; (void)n_in; (void)out_size;

    cudaFuncSetAttribute(proj_mma_kernel,
                         cudaFuncAttributeMaxDynamicSharedMemorySize, PROJ_SM_BYTES);
    cudaFuncSetAttribute(scores_mma_kernel,
                         cudaFuncAttributeMaxDynamicSharedMemorySize, SC_SM_BYTES);

    {
        int total4 = (int)(2 * (BLD / 4) + 2 * (DD / 4));
        split_all_kernel<<<(total4 + 255) / 256, 256>>>(query, key, wq_w, wk_w);
    }

    dim3 pgrid(D / 256, (B * L) / 128, 2);       // (3, 24, 2)
    proj_mma_kernel<<<pgrid, 512, PROJ_SM_BYTES>>>(wq_b, wk_b);

    dim3 sgrid(L / 256, L / 128, B * H);         // (6, 12, 24)
    scores_mma_kernel<<<sgrid, 512, SC_SM_BYTES>>>();

    // launch index 3 (0-based) — ncu captures this one
    entmax_warp_kernel<<<(B * L) / 4, 128>>>(mask, out);
}

// round 9
// speedup vs baseline: 1.8128x; 1.0026x over previous
#include <cuda_runtime.h>
#include <cuda_bf16.h>
#include <cstdint>

#define B 2
#define L 1536
#define D 768
#define H 12
#define DK 64
#define BLD ((size_t)B * L * D)
#define DD  ((size_t)D * D)

// ---------------------------------------------------------------------------
// Scratch (allocation-free rule: static __device__ arrays)
// ---------------------------------------------------------------------------
__device__ __nv_bfloat16 g_xqh[BLD], g_xql[BLD];
__device__ __nv_bfloat16 g_xkh[BLD], g_xkl[BLD];
__device__ __nv_bfloat16 g_wqh[DD],  g_wql[DD];
__device__ __nv_bfloat16 g_wkh[DD],  g_wkl[DD];
__device__ __nv_bfloat16 g_qh[BLD], g_ql[BLD];
__device__ __nv_bfloat16 g_kh[BLD], g_kl[BLD];
__device__ float g_s[(size_t)B * H * L * L];                // 226.5 MB

__device__ __forceinline__ uint32_t smem_u32(const void* p) {
    uint32_t a;
    asm("{ .reg .u64 t; cvta.to.shared.u64 t, %1; cvt.u32.u64 %0, t; }" : "=r"(a) : "l"(p));
    return a;
}
__device__ __forceinline__ void ldsm_x4(uint32_t addr, uint32_t& r0, uint32_t& r1,
                                        uint32_t& r2, uint32_t& r3) {
    asm volatile("ldmatrix.sync.aligned.m8n8.x4.shared.b16 {%0,%1,%2,%3}, [%4];"
                 : "=r"(r0), "=r"(r1), "=r"(r2), "=r"(r3) : "r"(addr));
}
__device__ __forceinline__ void ldsm_x2(uint32_t addr, uint32_t& r0, uint32_t& r1) {
    asm volatile("ldmatrix.sync.aligned.m8n8.x2.shared.b16 {%0,%1}, [%2];"
                 : "=r"(r0), "=r"(r1) : "r"(addr));
}
__device__ __forceinline__ void mma_bf16(float* c, const uint32_t* a, const uint32_t* b) {
    asm volatile(
        "mma.sync.aligned.m16n8k16.row.col.f32.bf16.bf16.f32 "
        "{%0,%1,%2,%3}, {%4,%5,%6,%7}, {%8,%9}, {%0,%1,%2,%3};"
        : "+f"(c[0]), "+f"(c[1]), "+f"(c[2]), "+f"(c[3])
        : "r"(a[0]), "r"(a[1]), "r"(a[2]), "r"(a[3]), "r"(b[0]), "r"(b[1]));
}
__device__ __forceinline__ void cpa16(uint32_t s, const void* g) {
    asm volatile("cp.async.cg.shared.global [%0], [%1], 16;" :: "r"(s), "l"(g));
}
#define CPA_COMMIT() asm volatile("cp.async.commit_group;" ::: "memory")
#define CPA_WAIT1()  asm volatile("cp.async.wait_group 1;" ::: "memory")
#define CPA_WAIT0()  asm volatile("cp.async.wait_group 0;" ::: "memory")

// ---------------------------------------------------------------------------
// Phase 0: fp32 -> bf16 hi/lo split of ALL four sources, ONE launch.
// ---------------------------------------------------------------------------
__global__ void split_all_kernel(const float* __restrict__ query,
                                 const float* __restrict__ key,
                                 const float* __restrict__ wq,
                                 const float* __restrict__ wk)
{
    const int n4x = (int)(BLD / 4);
    const int n4w = (int)(DD / 4);
    int i = blockIdx.x * blockDim.x + threadIdx.x;

    const float* src;
    __nv_bfloat16 *dh, *dl;
    int li;
    if (i < 2 * n4x) {
        if (i < n4x) { src = query; dh = g_xqh; dl = g_xql; li = i; }
        else         { src = key;   dh = g_xkh; dl = g_xkl; li = i - n4x; }
    } else {
        int j = i - 2 * n4x;
        if (j >= 2 * n4w) return;
        if (j < n4w) { src = wq; dh = g_wqh; dl = g_wql; li = j; }
        else         { src = wk; dh = g_wkh; dl = g_wkl; li = j - n4w; }
    }

    float4 v = ((const float4*)src)[li];
    __nv_bfloat16 h[4], l[4];
    const float* f = &v.x;
    #pragma unroll
    for (int j = 0; j < 4; j++) {
        h[j] = __float2bfloat16(f[j]);
        l[j] = __float2bfloat16(f[j] - __bfloat162float(h[j]));
    }
    ((uint2*)dh)[li] = *(uint2*)h;
    ((uint2*)dl)[li] = *(uint2*)l;
}

// ---------------------------------------------------------------------------
// Phase 1: projection via HMMA bf16x3, cp.async double-buffered K loop.
// ---------------------------------------------------------------------------
#define RP 72
#define P_AH 0
#define P_AL (128 * RP)
#define P_BH (2 * 128 * RP)
#define P_BL (2 * 128 * RP + 256 * RP)
#define PROJ_BUF (2 * 128 * RP + 2 * 256 * RP)
#define PROJ_SM_BYTES (2 * PROJ_BUF * 2)

__global__ void __launch_bounds__(512, 1) proj_mma_kernel(
    const float* __restrict__ biasq, const float* __restrict__ biask)
{
    extern __shared__ __nv_bfloat16 sm[];
    const uint32_t sm_b = smem_u32(sm);

    int nt = blockIdx.x, mt = blockIdx.y, which = blockIdx.z;
    int tid = threadIdx.x;
    int wid = tid >> 5, lane = tid & 31;

    const __nv_bfloat16* xh = which ? g_xkh : g_xqh;
    const __nv_bfloat16* xl = which ? g_xkl : g_xql;
    const __nv_bfloat16* wh = which ? g_wkh : g_wqh;
    const __nv_bfloat16* wl = which ? g_wkl : g_wql;
    __nv_bfloat16* oh = which ? g_kh : g_qh;
    __nv_bfloat16* ol = which ? g_kl : g_ql;
    const float* bias = which ? biask : biasq;

    int wm = (wid & 1) * 64;
    int wn = (wid >> 1) * 32;

    float acc[4][4][4];
    #pragma unroll
    for (int i = 0; i < 4; i++)
        #pragma unroll
        for (int j = 0; j < 4; j++)
            #pragma unroll
            for (int r = 0; r < 4; r++) acc[i][j][r] = 0.f;

    int a_row = lane & 15;
    int a_kh8 = (lane >> 4) * 8;
    int b_row = lane & 7;
    int b_kh8 = ((lane >> 3) & 1) * 8;

    int lrowA[2], lc8A[2], lrowB[4], lc8B[4];
    #pragma unroll
    for (int it = 0; it < 2; it++) { int idx = tid + it * 512; lrowA[it] = idx >> 3; lc8A[it] = (idx & 7) * 8; }
    #pragma unroll
    for (int it = 0; it < 4; it++) { int idx = tid + it * 512; lrowB[it] = idx >> 3; lc8B[it] = (idx & 7) * 8; }

    auto prefetch = [&](int kc, int pb) {
        uint32_t base = sm_b + (uint32_t)pb * PROJ_BUF * 2;
        #pragma unroll
        for (int it = 0; it < 2; it++) {
            size_t g = (size_t)(mt * 128 + lrowA[it]) * D + kc + lc8A[it];
            uint32_t so = (uint32_t)(lrowA[it] * RP + lc8A[it]) * 2;
            cpa16(base + P_AH * 2 + so, xh + g);
            cpa16(base + P_AL * 2 + so, xl + g);
        }
        #pragma unroll
        for (int it = 0; it < 4; it++) {
            size_t g = (size_t)(nt * 256 + lrowB[it]) * D + kc + lc8B[it];
            uint32_t so = (uint32_t)(lrowB[it] * RP + lc8B[it]) * 2;
            cpa16(base + P_BH * 2 + so, wh + g);
            cpa16(base + P_BL * 2 + so, wl + g);
        }
        CPA_COMMIT();
    };

    prefetch(0, 0);

    int buf = 0;
    for (int kci = 0; kci < 12; kci++) {
        if (kci < 11) { prefetch((kci + 1) * 64, buf ^ 1); CPA_WAIT1(); }
        else          { CPA_WAIT0(); }
        __syncthreads();

        uint32_t base = sm_b + (uint32_t)buf * PROJ_BUF * 2;
        uint32_t sAh_b = base + P_AH * 2, sAl_b = base + P_AL * 2;
        uint32_t sBh_b = base + P_BH * 2, sBl_b = base + P_BL * 2;

        #pragma unroll
        for (int ks = 0; ks < 4; ks++) {
            int kb = ks * 16;
            uint32_t ah[4][4], al[4][4];
            #pragma unroll
            for (int i = 0; i < 4; i++) {
                uint32_t off = (uint32_t)((wm + i * 16 + a_row) * RP + kb + a_kh8) * 2;
                ldsm_x4(sAh_b + off, ah[i][0], ah[i][1], ah[i][2], ah[i][3]);
                ldsm_x4(sAl_b + off, al[i][0], al[i][1], al[i][2], al[i][3]);
            }
            #pragma unroll
            for (int j = 0; j < 4; j++) {
                uint32_t off = (uint32_t)((wn + j * 8 + b_row) * RP + kb + b_kh8) * 2;
                uint32_t bh[2], bl[2];
                ldsm_x2(sBh_b + off, bh[0], bh[1]);
                ldsm_x2(sBl_b + off, bl[0], bl[1]);
                #pragma unroll
                for (int i = 0; i < 4; i++) {
                    mma_bf16(acc[i][j], ah[i], bh);
                    mma_bf16(acc[i][j], ah[i], bl);
                    mma_bf16(acc[i][j], al[i], bh);
                }
            }
        }
        __syncthreads();
        buf ^= 1;
    }

    int r0 = lane >> 2;
    int cp = (lane & 3) * 2;
    #pragma unroll
    for (int i = 0; i < 4; i++) {
        int grow0 = mt * 128 + wm + i * 16 + r0;
        #pragma unroll
        for (int j = 0; j < 4; j++) {
            int gcol = nt * 256 + wn + j * 8 + cp;
            float2 bv = *(const float2*)(bias + gcol);
            #pragma unroll
            for (int half = 0; half < 2; half++) {
                float v0 = acc[i][j][half * 2 + 0] + bv.x;
                float v1 = acc[i][j][half * 2 + 1] + bv.y;
                __nv_bfloat16 h0 = __float2bfloat16(v0);
                __nv_bfloat16 h1 = __float2bfloat16(v1);
                __nv_bfloat16 l0 = __float2bfloat16(v0 - __bfloat162float(h0));
                __nv_bfloat16 l1 = __float2bfloat16(v1 - __bfloat162float(h1));
                size_t addr = (size_t)(grow0 + half * 8) * D + gcol;
                __nv_bfloat16 hp[2] = {h0, h1}, lp[2] = {l0, l1};
                *(uint32_t*)(oh + addr) = *(uint32_t*)hp;
                *(uint32_t*)(ol + addr) = *(uint32_t*)lp;
            }
        }
    }
}

// ---------------------------------------------------------------------------
// Phase 2: scores via HMMA bf16x3.
// ---------------------------------------------------------------------------
#define SC_SM_Q (128 * RP)
#define SC_SM_K (256 * RP)
#define SC_SM_BYTES ((2 * SC_SM_Q + 2 * SC_SM_K) * 2)

__global__ void __launch_bounds__(512, 1) scores_mma_kernel()
{
    extern __shared__ __nv_bfloat16 sm[];
    __nv_bfloat16* sQh = sm;
    __nv_bfloat16* sQl = sm + SC_SM_Q;
    __nv_bfloat16* sKh = sm + 2 * SC_SM_Q;
    __nv_bfloat16* sKl = sm + 2 * SC_SM_Q + SC_SM_K;

    int kt = blockIdx.x, qt = blockIdx.y, bh = blockIdx.z;
    int b = bh / H, h = bh % H;
    int tid = threadIdx.x;
    int wid = tid >> 5, lane = tid & 31;

    {
        const __nv_bfloat16* qhb = g_qh + (size_t)(b * L + qt * 128) * D + h * DK;
        const __nv_bfloat16* qlb = g_ql + (size_t)(b * L + qt * 128) * D + h * DK;
        const __nv_bfloat16* khb = g_kh + (size_t)(b * L + kt * 256) * D + h * DK;
        const __nv_bfloat16* klb = g_kl + (size_t)(b * L + kt * 256) * D + h * DK;

        #pragma unroll
        for (int it = 0; it < 2; it++) {
            int idx = tid + it * 512;
            int row = idx >> 3;
            int c8  = (idx & 7) * 8;
            *(uint4*)(sQh + row * RP + c8) = *(const uint4*)(qhb + (size_t)row * D + c8);
            *(uint4*)(sQl + row * RP + c8) = *(const uint4*)(qlb + (size_t)row * D + c8);
        }
        #pragma unroll
        for (int it = 0; it < 4; it++) {
            int idx = tid + it * 512;
            int row = idx >> 3;
            int c8  = (idx & 7) * 8;
            *(uint4*)(sKh + row * RP + c8) = *(const uint4*)(khb + (size_t)row * D + c8);
            *(uint4*)(sKl + row * RP + c8) = *(const uint4*)(klb + (size_t)row * D + c8);
        }
    }
    __syncthreads();

    int wm = (wid & 1) * 64;
    int wn = (wid >> 1) * 32;

    float acc[4][4][4];
    #pragma unroll
    for (int i = 0; i < 4; i++)
        #pragma unroll
        for (int j = 0; j < 4; j++)
            #pragma unroll
            for (int r = 0; r < 4; r++) acc[i][j][r] = 0.f;

    uint32_t sQh_b = smem_u32(sQh), sQl_b = smem_u32(sQl);
    uint32_t sKh_b = smem_u32(sKh), sKl_b = smem_u32(sKl);

    int a_row = lane & 15;
    int a_kh8 = (lane >> 4) * 8;
    int b_row = lane & 7;
    int b_kh8 = ((lane >> 3) & 1) * 8;

    #pragma unroll
    for (int ks = 0; ks < 4; ks++) {
        int kb = ks * 16;
        uint32_t ah[4][4], al[4][4];
        #pragma unroll
        for (int i = 0; i < 4; i++) {
            uint32_t off = (uint32_t)((wm + i * 16 + a_row) * RP + kb + a_kh8) * 2;
            ldsm_x4(sQh_b + off, ah[i][0], ah[i][1], ah[i][2], ah[i][3]);
            ldsm_x4(sQl_b + off, al[i][0], al[i][1], al[i][2], al[i][3]);
        }
        #pragma unroll
        for (int j = 0; j < 4; j++) {
            uint32_t off = (uint32_t)((wn + j * 8 + b_row) * RP + kb + b_kh8) * 2;
            uint32_t bh2[2], bl2[2];
            ldsm_x2(sKh_b + off, bh2[0], bh2[1]);
            ldsm_x2(sKl_b + off, bl2[0], bl2[1]);
            #pragma unroll
            for (int i = 0; i < 4; i++) {
                mma_bf16(acc[i][j], ah[i], bh2);
                mma_bf16(acc[i][j], ah[i], bl2);
                mma_bf16(acc[i][j], al[i], bh2);
            }
        }
    }

    const float scale = 1.0f / 16.0f;
    int r0 = lane >> 2;
    int cp = (lane & 3) * 2;
    #pragma unroll
    for (int i = 0; i < 4; i++) {
        int grow0 = qt * 128 + wm + i * 16 + r0;
        #pragma unroll
        for (int j = 0; j < 4; j++) {
            int gcol = kt * 256 + wn + j * 8 + cp;
            float2 v0 = make_float2(acc[i][j][0] * scale, acc[i][j][1] * scale);
            float2 v1 = make_float2(acc[i][j][2] * scale, acc[i][j][3] * scale);
            *(float2*)(g_s + ((size_t)bh * L + grow0) * L + gcol) = v0;
            *(float2*)(g_s + ((size_t)bh * L + grow0 + 8) * L + gcol) = v1;
        }
    }
}

// ---------------------------------------------------------------------------
// Phase 3: entmax-1.5, warp per row. Accelerated root-find:
// Newton on sqrt(f) while far (s0>2; sqrt(f) is ~linear far from the root),
// standard Newton near/after overshoot (globally convergent on convex f).
// ---------------------------------------------------------------------------
__global__ void __launch_bounds__(128) entmax_warp_kernel(
    const int* __restrict__ mask, float* __restrict__ out)
{
    int warp = (blockIdx.x * blockDim.x + threadIdx.x) >> 5;
    int lane = threadIdx.x & 31;
    int b = warp / L, qi = warp % L;

    unsigned long long vbits = 0ull;
    {
        const int4* mrow = (const int4*)(mask + b * L);
        #pragma unroll
        for (int i = 0; i < 12; i++) {
            int4 mv = mrow[lane + i * 32];
            if (mv.x) vbits |= 1ull << (i * 4 + 0);
            if (mv.y) vbits |= 1ull << (i * 4 + 1);
            if (mv.z) vbits |= 1ull << (i * 4 + 2);
            if (mv.w) vbits |= 1ull << (i * 4 + 3);
        }
    }

    float acc[48];
    #pragma unroll
    for (int e = 0; e < 48; e++) acc[e] = 0.f;

    const float invH = 1.0f / 12.0f;

    for (int h = 0; h < H; h++) {
        const float4* row = (const float4*)(g_s + ((size_t)(b * H + h) * L + qi) * L);
        float z[48];
        float m = -1e30f;
        #pragma unroll
        for (int i = 0; i < 12; i++) {
            float4 v = __ldg(row + lane + i * 32);
            z[i * 4 + 0] = (vbits >> (i * 4 + 0)) & 1 ? v.x : -1e30f;
            z[i * 4 + 1] = (vbits >> (i * 4 + 1)) & 1 ? v.y : -1e30f;
            z[i * 4 + 2] = (vbits >> (i * 4 + 2)) & 1 ? v.z : -1e30f;
            z[i * 4 + 3] = (vbits >> (i * 4 + 3)) & 1 ? v.w : -1e30f;
            m = fmaxf(m, fmaxf(fmaxf(z[i * 4], z[i * 4 + 1]), fmaxf(z[i * 4 + 2], z[i * 4 + 3])));
        }
        #pragma unroll
        for (int o = 16; o; o >>= 1) m = fmaxf(m, __shfl_xor_sync(0xffffffffu, m, o));

        float tau = m - 1.0f;        // f(tau0) >= 1 (root is to the right)
        const float tmax = m - 1e-7f;

        for (int it = 0; it < 20; it++) {
            float s0 = 0.f, s1 = 0.f;
            #pragma unroll
            for (int e = 0; e < 48; e++) {
                float d = fmaxf(z[e] - tau, 0.f);
                s1 += d;
                s0 = fmaf(d, d, s0);
            }
            #pragma unroll
            for (int o = 16; o; o >>= 1) {
                s0 += __shfl_xor_sync(0xffffffffu, s0, o);
                s1 += __shfl_xor_sync(0xffffffffu, s1, o);
            }
            float step;
            if (s0 > 2.0f) {
                // Newton on sqrt(f): tau += (s0 - sqrt(s0)) / s1
                step = (s0 - sqrtf(s0)) / s1;
            } else {
                // standard Newton on f (monotone-convergent on convex f)
                step = (s0 - 1.0f) / (2.0f * s1);
            }
            tau = fminf(tau + step, tmax);
            if (fabsf(step) <= 5e-7f) break;
        }

        #pragma unroll
        for (int e = 0; e < 48; e++) {
            float d = z[e] - tau;
            if (d > 0.f) acc[e] = fmaf(d * d, invH, acc[e]);
        }
    }

    float4* orow = (float4*)(out + ((size_t)b * L + qi) * L);
    #pragma unroll
    for (int i = 0; i < 12; i++) {
        float4 v;
        v.x = acc[i * 4 + 0]; v.y = acc[i * 4 + 1];
        v.z = acc[i * 4 + 2]; v.w = acc[i * 4 + 3];
        orow[lane + i * 32] = v;
    }
}

// ---------------------------------------------------------------------------
extern "C" void kernel_launch(void* const* d_in, const int* in_sizes, int n_in,
                              void* d_out, int out_size)
{
    const float* query = (const float*)d_in[0];
    const float* key   = (const float*)d_in[1];
    const int*   mask  = (const int*)d_in[2];
    const float* wq_w  = (const float*)d_in[3];
    const float* wq_b  = (const float*)d_in[4];
    const float* wk_w  = (const float*)d_in[5];
    const float* wk_b  = (const float*)d_in[6];
    float* out = (float*)d_out;

    (void)in_sizes; (void)n_in; (void)out_size;

    cudaFuncSetAttribute(proj_mma_kernel,
                         cudaFuncAttributeMaxDynamicSharedMemorySize, PROJ_SM_BYTES);
    cudaFuncSetAttribute(scores_mma_kernel,
                         cudaFuncAttributeMaxDynamicSharedMemorySize, SC_SM_BYTES);

    {
        int total4 = (int)(2 * (BLD / 4) + 2 * (DD / 4));
        split_all_kernel<<<(total4 + 255) / 256, 256>>>(query, key, wq_w, wk_w);
    }

    dim3 pgrid(D / 256, (B * L) / 128, 2);       // (3, 24, 2)
    proj_mma_kernel<<<pgrid, 512, PROJ_SM_BYTES>>>(wq_b, wk_b);

    dim3 sgrid(L / 256, L / 128, B * H);         // (6, 12, 24)
    scores_mma_kernel<<<sgrid, 512, SC_SM_BYTES>>>();

    // launch index 3 (0-based) — ncu captures this one
    entmax_warp_kernel<<<(B * L) / 4, 128>>>(mask, out);
}